// round 1
// baseline (speedup 1.0000x reference)
#include <cuda_runtime.h>

#define NB 128
#define C 64
#define T 1024
#define TILE 128

// Scratch for Q, K, V projections (module-load allocation, allowed).
__device__ float g_Q[NB * C * T];
__device__ float g_K[NB * C * T];
__device__ float g_V[NB * C * T];

// ---------------------------------------------------------------------------
// Kernel 1: QKV projection.  grid (8 tiles, 128 batches), 256 threads.
// q[o][t] = sum_c Wq[o][c] * x[c][t]  (same for k, v)
// ---------------------------------------------------------------------------
extern "C" __global__ void __launch_bounds__(256, 1)
qkv_kernel(const float* __restrict__ x,
           const float* __restrict__ Wq,
           const float* __restrict__ Wk,
           const float* __restrict__ Wv)
{
    extern __shared__ float sm[];
    float* xs = sm;               // 64*128 floats
    float* Ws = sm + 64 * 128;    // 3 * 64*64 floats

    const int j = blockIdx.x;     // t tile
    const int n = blockIdx.y;     // batch
    const int tid = threadIdx.x;

    const float* xb = x + (size_t)n * C * T + j * TILE;

    // load x tile [64][128], coalesced
#pragma unroll
    for (int i = 0; i < 32; i++) {
        int idx = i * 256 + tid;
        xs[idx] = xb[(idx >> 7) * T + (idx & 127)];
    }
    // load the three weight matrices
    for (int idx = tid; idx < 4096; idx += 256) {
        Ws[idx]        = Wq[idx];
        Ws[4096 + idx] = Wk[idx];
        Ws[8192 + idx] = Wv[idx];
    }
    __syncthreads();

    const int co  = tid >> 5;   // 0..7  -> c_out block of 8
    const int tq  = tid & 31;   // 0..31 -> t block of 4
    const float4* xs4 = (const float4*)xs;

    for (int m = 0; m < 3; m++) {
        float acc[8][4];
#pragma unroll
        for (int i = 0; i < 8; i++)
#pragma unroll
            for (int k = 0; k < 4; k++) acc[i][k] = 0.f;

        const float* Wm = Ws + m * 4096;
#pragma unroll 8
        for (int c = 0; c < 64; c++) {
            float4 xv = xs4[c * 32 + tq];
#pragma unroll
            for (int i = 0; i < 8; i++) {
                float w = Wm[(co * 8 + i) * 64 + c];
                acc[i][0] += w * xv.x;
                acc[i][1] += w * xv.y;
                acc[i][2] += w * xv.z;
                acc[i][3] += w * xv.w;
            }
        }
        float* dst = (m == 0 ? g_Q : (m == 1 ? g_K : g_V))
                     + (size_t)n * C * T + j * TILE;
#pragma unroll
        for (int i = 0; i < 8; i++) {
            float4 v = make_float4(acc[i][0], acc[i][1], acc[i][2], acc[i][3]);
            *(float4*)&dst[(co * 8 + i) * T + tq * 4] = v;
        }
    }
}

// ---------------------------------------------------------------------------
// Kernel 2: flash attention over time axis + output projection + residual.
// grid (8 query tiles, 128 batches), 256 threads.
// ---------------------------------------------------------------------------
extern "C" __global__ void __launch_bounds__(256, 1)
attn_kernel(const float* __restrict__ x,
            const float* __restrict__ Wo,
            const float* __restrict__ scale_p,
            float* __restrict__ out)
{
    extern __shared__ float sm[];
    float* Qs   = sm;            // 8192  (later reused as Os[c][tq])
    float* Ks   = Qs + 8192;     // 8192  (later reused as Wo smem)
    float* Vs   = Ks + 8192;     // 8192
    float* Ps   = Vs + 8192;     // 128*129 = 16512 (P transposed: Ps[s][tq])
    float* mrow = Ps + 16512;    // 128
    float* lrow = mrow + 128;    // 128
    float* cfs  = lrow + 128;    // 128

    const int j = blockIdx.x;
    const int n = blockIdx.y;
    const int tid = threadIdx.x;
    const float scale = *scale_p;

    // load Q tile [64][128]
    const float* qb = g_Q + (size_t)n * C * T + j * TILE;
#pragma unroll
    for (int i = 0; i < 32; i++) {
        int idx = i * 256 + tid;
        Qs[idx] = qb[(idx >> 7) * T + (idx & 127)];
    }
    if (tid < 128) { mrow[tid] = -1e30f; lrow[tid] = 0.f; }

    // phase A map: 16x16 threads; each does 8 tq rows x 8 s cols
    const int tx = tid & 15;
    const int ty = tid >> 4;
    // phase B map: each thread: 8 tq x 4 c accumulators
    const int tqB = (tid & 15) * 8;
    const int cB  = (tid >> 4) * 4;

    float acc[8][4];
#pragma unroll
    for (int i = 0; i < 8; i++)
#pragma unroll
        for (int k = 0; k < 4; k++) acc[i][k] = 0.f;

    for (int st = 0; st < 8; st++) {
        __syncthreads();   // prev phase B finished; safe to overwrite Ks/Vs/Ps
        const float* kb = g_K + (size_t)n * C * T + st * TILE;
        const float* vb = g_V + (size_t)n * C * T + st * TILE;
#pragma unroll
        for (int i = 0; i < 32; i++) {
            int idx = i * 256 + tid;
            int c = idx >> 7, t = idx & 127;
            Ks[idx] = kb[c * T + t];
            Vs[idx] = vb[c * T + t];
        }
        __syncthreads();

        // ---- scores S[8][8] ----
        float S[8][8];
#pragma unroll
        for (int r = 0; r < 8; r++)
#pragma unroll
            for (int s = 0; s < 8; s++) S[r][s] = 0.f;

#pragma unroll 4
        for (int c = 0; c < 64; c++) {
            float4 qa = *(const float4*)&Qs[c * 128 + ty * 8];
            float4 qc = *(const float4*)&Qs[c * 128 + ty * 8 + 4];
            float4 ka = *(const float4*)&Ks[c * 128 + tx * 8];
            float4 kc = *(const float4*)&Ks[c * 128 + tx * 8 + 4];
            float qv[8] = {qa.x, qa.y, qa.z, qa.w, qc.x, qc.y, qc.z, qc.w};
            float kv[8] = {ka.x, ka.y, ka.z, ka.w, kc.x, kc.y, kc.z, kc.w};
#pragma unroll
            for (int r = 0; r < 8; r++)
#pragma unroll
                for (int s = 0; s < 8; s++) S[r][s] += qv[r] * kv[s];
        }

        // ---- online softmax ----
        float mold[8], mnew[8], lt[8];
#pragma unroll
        for (int r = 0; r < 8; r++) {
            float mx = -1e30f;
#pragma unroll
            for (int s = 0; s < 8; s++) {
                S[r][s] *= scale;
                mx = fmaxf(mx, S[r][s]);
            }
#pragma unroll
            for (int o = 8; o; o >>= 1)
                mx = fmaxf(mx, __shfl_xor_sync(0xffffffffu, mx, o));
            mold[r] = mrow[ty * 8 + r];
            mnew[r] = fmaxf(mold[r], mx);
            float sum = 0.f;
#pragma unroll
            for (int s = 0; s < 8; s++) {
                S[r][s] = __expf(S[r][s] - mnew[r]);
                sum += S[r][s];
            }
#pragma unroll
            for (int o = 8; o; o >>= 1)
                sum += __shfl_xor_sync(0xffffffffu, sum, o);
            lt[r] = sum;
        }
        __syncthreads();   // all mrow reads done before updates
        if (tx == 0) {
#pragma unroll
            for (int r = 0; r < 8; r++) {
                int tq = ty * 8 + r;
                float cf = __expf(mold[r] - mnew[r]);
                mrow[tq] = mnew[r];
                lrow[tq] = lrow[tq] * cf + lt[r];
                cfs[tq]  = cf;
            }
        }
        // write P transposed: Ps[s][tq]
#pragma unroll
        for (int s = 0; s < 8; s++)
#pragma unroll
            for (int r = 0; r < 8; r++)
                Ps[(tx * 8 + s) * 129 + ty * 8 + r] = S[r][s];
        __syncthreads();

        // ---- phase B: O[c][tq] += P[tq][s] * V[c][s], with rescale ----
#pragma unroll
        for (int i = 0; i < 8; i++) {
            float cf = cfs[tqB + i];
#pragma unroll
            for (int k = 0; k < 4; k++) acc[i][k] *= cf;
        }
#pragma unroll 4
        for (int s = 0; s < 128; s++) {
            float p[8], v[4];
#pragma unroll
            for (int i = 0; i < 8; i++) p[i] = Ps[s * 129 + tqB + i];
#pragma unroll
            for (int k = 0; k < 4; k++) v[k] = Vs[(cB + k) * 128 + s];
#pragma unroll
            for (int i = 0; i < 8; i++)
#pragma unroll
                for (int k = 0; k < 4; k++) acc[i][k] += p[i] * v[k];
        }
    }
    __syncthreads();

    // normalize; write attention output to Qs region as Os[c][tq]
    float linv[8];
#pragma unroll
    for (int i = 0; i < 8; i++) linv[i] = 1.f / lrow[tqB + i];
#pragma unroll
    for (int i = 0; i < 8; i++)
#pragma unroll
        for (int k = 0; k < 4; k++)
            Qs[(cB + k) * 128 + tqB + i] = acc[i][k] * linv[i];

    // Wo into Ks region
    for (int idx = tid; idx < 4096; idx += 256) Ks[idx] = Wo[idx];
    __syncthreads();

    // final projection + residual
    const int co  = tid >> 5;
    const int tq4 = tid & 31;
    float o2[8][4];
#pragma unroll
    for (int i = 0; i < 8; i++)
#pragma unroll
        for (int k = 0; k < 4; k++) o2[i][k] = 0.f;

#pragma unroll 8
    for (int c = 0; c < 64; c++) {
        float4 xv = *(const float4*)&Qs[c * 128 + tq4 * 4];
#pragma unroll
        for (int i = 0; i < 8; i++) {
            float w = Ks[(co * 8 + i) * 64 + c];
            o2[i][0] += w * xv.x;
            o2[i][1] += w * xv.y;
            o2[i][2] += w * xv.z;
            o2[i][3] += w * xv.w;
        }
    }
    const float* xb = x + (size_t)n * C * T + j * TILE;
    float* ob = out + (size_t)n * C * T + j * TILE;
#pragma unroll
    for (int i = 0; i < 8; i++) {
        float4 xr = *(const float4*)&xb[(co * 8 + i) * T + tq4 * 4];
        float4 res = make_float4(o2[i][0] + xr.x, o2[i][1] + xr.y,
                                 o2[i][2] + xr.z, o2[i][3] + xr.w);
        *(float4*)&ob[(co * 8 + i) * T + tq4 * 4] = res;
    }
}

// ---------------------------------------------------------------------------
extern "C" void kernel_launch(void* const* d_in, const int* in_sizes, int n_in,
                              void* d_out, int out_size)
{
    const float* x     = (const float*)d_in[0];
    const float* Wq    = (const float*)d_in[1];
    const float* Wk    = (const float*)d_in[2];
    const float* Wv    = (const float*)d_in[3];
    const float* Wo    = (const float*)d_in[4];
    const float* scale = (const float*)d_in[5];
    float* out = (float*)d_out;

    const int smem1 = (64 * 128 + 3 * 64 * 64) * 4;                 // 81920 B
    const int smem2 = (3 * 8192 + 128 * 129 + 3 * 128) * 4;         // 165888 B
    cudaFuncSetAttribute(qkv_kernel,  cudaFuncAttributeMaxDynamicSharedMemorySize, smem1);
    cudaFuncSetAttribute(attn_kernel, cudaFuncAttributeMaxDynamicSharedMemorySize, smem2);

    dim3 grid(8, 128);
    qkv_kernel<<<grid, 256, smem1>>>(x, Wq, Wk, Wv);
    attn_kernel<<<grid, 256, smem2>>>(x, Wo, scale, out);
}

// round 2
// speedup vs baseline: 2.9719x; 2.9719x over previous
#include <cuda_runtime.h>
#include <cstdint>

#define NB 128
#define C 64
#define T 1024
#define TILE 128
#define NT 8           // number of 128-wide tiles in T

// Scratch: Q and K stored t-major [n][t][c] (tf32-rounded), V native [n][c][t].
__device__ float g_Qt[NB * T * C];
__device__ float g_Kt[NB * T * C];
__device__ float g_V [NB * C * T];

__device__ __forceinline__ float tf32r(float x) {
    uint32_t r;
    asm("cvt.rna.tf32.f32 %0, %1;" : "=r"(r) : "f"(x));
    return __uint_as_float(r);
}
__device__ __forceinline__ float ex2a(float x) {
    float y;
    asm("ex2.approx.ftz.f32 %0, %1;" : "=f"(y) : "f"(x));
    return y;
}
__device__ __forceinline__ uint32_t fu(float x) { return __float_as_uint(x); }

#define MMA_TF32(d, a0, a1, a2, a3, b0, b1)                                   \
    asm volatile(                                                             \
        "mma.sync.aligned.m16n8k8.row.col.f32.tf32.tf32.f32 "                 \
        "{%0,%1,%2,%3}, {%4,%5,%6,%7}, {%8,%9}, {%0,%1,%2,%3};"               \
        : "+f"(d[0]), "+f"(d[1]), "+f"(d[2]), "+f"(d[3])                      \
        : "r"(a0), "r"(a1), "r"(a2), "r"(a3), "r"(b0), "r"(b1))

// ---------------------------------------------------------------------------
// Kernel 1: QKV projection -> tf32 scratch.  grid (8, 128), 256 threads.
// Q gets scale*log2(e) folded in (softmax done in exp2 domain).
// ---------------------------------------------------------------------------
extern "C" __global__ void __launch_bounds__(256, 1)
qkv_kernel(const float* __restrict__ x,
           const float* __restrict__ Wq,
           const float* __restrict__ Wk,
           const float* __restrict__ Wv,
           const float* __restrict__ scale_p)
{
    extern __shared__ float sm[];
    float* xs = sm;               // 64*128
    float* Ws = sm + 64 * 128;    // 3 * 64*64

    const int j = blockIdx.x;
    const int n = blockIdx.y;
    const int tid = threadIdx.x;
    const float qs = scale_p[0] * 1.44269504088896f;

    const float* xb = x + (size_t)n * C * T + j * TILE;
#pragma unroll
    for (int i = 0; i < 32; i++) {
        int idx = i * 256 + tid;
        xs[idx] = xb[(idx >> 7) * T + (idx & 127)];
    }
    for (int idx = tid; idx < 4096; idx += 256) {
        Ws[idx]        = Wq[idx];
        Ws[4096 + idx] = Wk[idx];
        Ws[8192 + idx] = Wv[idx];
    }
    __syncthreads();

    const int co = tid >> 5;
    const int tq = tid & 31;
    const float4* xs4 = (const float4*)xs;

    for (int m = 0; m < 3; m++) {
        float acc[8][4];
#pragma unroll
        for (int i = 0; i < 8; i++)
#pragma unroll
            for (int k = 0; k < 4; k++) acc[i][k] = 0.f;

        const float* Wm = Ws + m * 4096;
#pragma unroll 8
        for (int c = 0; c < 64; c++) {
            float4 xv = xs4[c * 32 + tq];
#pragma unroll
            for (int i = 0; i < 8; i++) {
                float w = Wm[(co * 8 + i) * 64 + c];
                acc[i][0] += w * xv.x;
                acc[i][1] += w * xv.y;
                acc[i][2] += w * xv.z;
                acc[i][3] += w * xv.w;
            }
        }

        if (m == 0) {
#pragma unroll
            for (int i = 0; i < 8; i++)
#pragma unroll
                for (int k = 0; k < 4; k++) acc[i][k] *= qs;
        }

        if (m < 2) {
            // transposed store: [t][c], tf32-rounded
            float* dstT = (m == 0 ? g_Qt : g_Kt) + ((size_t)n * T + j * TILE) * C;
#pragma unroll
            for (int k = 0; k < 4; k++) {
                int t = tq * 4 + k;
                float4 lo = make_float4(tf32r(acc[0][k]), tf32r(acc[1][k]),
                                        tf32r(acc[2][k]), tf32r(acc[3][k]));
                float4 hi = make_float4(tf32r(acc[4][k]), tf32r(acc[5][k]),
                                        tf32r(acc[6][k]), tf32r(acc[7][k]));
                *(float4*)&dstT[t * C + co * 8]     = lo;
                *(float4*)&dstT[t * C + co * 8 + 4] = hi;
            }
        } else {
            float* dst = g_V + (size_t)n * C * T + j * TILE;
#pragma unroll
            for (int i = 0; i < 8; i++) {
                float4 v = make_float4(tf32r(acc[i][0]), tf32r(acc[i][1]),
                                       tf32r(acc[i][2]), tf32r(acc[i][3]));
                *(float4*)&dst[(co * 8 + i) * T + tq * 4] = v;
            }
        }
    }
}

// ---------------------------------------------------------------------------
// Kernel 2: flash attention with tf32 mma.sync + Wo projection + residual.
// grid (8, 128), 256 threads = 8 warps, each warp owns 16 query rows.
// ---------------------------------------------------------------------------
extern "C" __global__ void __launch_bounds__(256, 1)
attn_kernel(const float* __restrict__ x,
            const float* __restrict__ Wo,
            float* __restrict__ out)
{
    extern __shared__ float sm[];
    float* Qs = sm;              // [128][68]  = 8704
    float* Ks = sm + 8704;       // [128][68]  = 8704   (later Wo [64][68])
    float* Vs = sm + 17408;      // [64][132]  = 8448   (later O^T [64][132])
    float* Ps = sm + 25856;      // [128][132] = 16896  (later O [tq][c])

    const int j = blockIdx.x;
    const int n = blockIdx.y;
    const int tid  = threadIdx.x;
    const int warp = tid >> 5;
    const int lane = tid & 31;
    const int g  = lane >> 2;     // row group 0..7
    const int c4 = lane & 3;      // col-in-group 0..3
    const int rbase = warp * 16;  // this warp's query rows

    // ---- load Q tile [128 tq][64 c] ----
    const float* qsrc = g_Qt + ((size_t)n * T + j * TILE) * C;
#pragma unroll
    for (int it = 0; it < 8; it++) {
        int flat = it * 1024 + tid * 4;
        float4 v = *(const float4*)(qsrc + flat);
        *(float4*)(Qs + (flat >> 6) * 68 + (flat & 63)) = v;
    }

    float m0 = -1e30f, m1 = -1e30f, l0 = 0.f, l1 = 0.f;
    float oacc[8][4];
#pragma unroll
    for (int i = 0; i < 8; i++)
#pragma unroll
        for (int k = 0; k < 4; k++) oacc[i][k] = 0.f;

    for (int st = 0; st < NT; st++) {
        __syncthreads();
        const float* ksrc = g_Kt + ((size_t)n * T + st * TILE) * C;
#pragma unroll
        for (int it = 0; it < 8; it++) {
            int flat = it * 1024 + tid * 4;
            float4 v = *(const float4*)(ksrc + flat);
            *(float4*)(Ks + (flat >> 6) * 68 + (flat & 63)) = v;
        }
        const float* vsrc = g_V + (size_t)n * C * T + st * TILE;
#pragma unroll
        for (int it = 0; it < 8; it++) {
            int flat = it * 1024 + tid * 4;
            int row = flat >> 7, t = flat & 127;
            float4 v = *(const float4*)(vsrc + row * T + t);
            *(float4*)(Vs + row * 132 + t) = v;
        }
        __syncthreads();

        // ---- S = Q K^T : per-warp m16 x n128 x k64 ----
        float sacc[16][4];
#pragma unroll
        for (int i = 0; i < 16; i++)
#pragma unroll
            for (int k = 0; k < 4; k++) sacc[i][k] = 0.f;

#pragma unroll
        for (int ks = 0; ks < 8; ks++) {
            const float* q0 = Qs + (rbase + g) * 68 + ks * 8 + c4;
            const float* q1 = Qs + (rbase + g + 8) * 68 + ks * 8 + c4;
            uint32_t a0 = fu(q0[0]), a1 = fu(q1[0]);
            uint32_t a2 = fu(q0[4]), a3 = fu(q1[4]);
#pragma unroll
            for (int nf = 0; nf < 16; nf++) {
                const float* kp = Ks + (nf * 8 + g) * 68 + ks * 8 + c4;
                uint32_t b0 = fu(kp[0]), b1 = fu(kp[4]);
                MMA_TF32(sacc[nf], a0, a1, a2, a3, b0, b1);
            }
        }

        // ---- online softmax (exp2 domain; scale folded into Q) ----
        float mx0 = -1e30f, mx1 = -1e30f;
#pragma unroll
        for (int nf = 0; nf < 16; nf++) {
            mx0 = fmaxf(mx0, fmaxf(sacc[nf][0], sacc[nf][1]));
            mx1 = fmaxf(mx1, fmaxf(sacc[nf][2], sacc[nf][3]));
        }
        mx0 = fmaxf(mx0, __shfl_xor_sync(0xffffffffu, mx0, 1));
        mx0 = fmaxf(mx0, __shfl_xor_sync(0xffffffffu, mx0, 2));
        mx1 = fmaxf(mx1, __shfl_xor_sync(0xffffffffu, mx1, 1));
        mx1 = fmaxf(mx1, __shfl_xor_sync(0xffffffffu, mx1, 2));

        float nm0 = fmaxf(m0, mx0), nm1 = fmaxf(m1, mx1);
        float cf0 = ex2a(m0 - nm0), cf1 = ex2a(m1 - nm1);
        m0 = nm0; m1 = nm1;

        float ls0 = 0.f, ls1 = 0.f;
        float* prow0 = Ps + (rbase + g) * 132;
        float* prow1 = Ps + (rbase + g + 8) * 132;
#pragma unroll
        for (int nf = 0; nf < 16; nf++) {
            float p00 = ex2a(sacc[nf][0] - nm0);
            float p01 = ex2a(sacc[nf][1] - nm0);
            float p10 = ex2a(sacc[nf][2] - nm1);
            float p11 = ex2a(sacc[nf][3] - nm1);
            ls0 += p00 + p01;
            ls1 += p10 + p11;
            *(float2*)(prow0 + nf * 8 + 2 * c4) = make_float2(tf32r(p00), tf32r(p01));
            *(float2*)(prow1 + nf * 8 + 2 * c4) = make_float2(tf32r(p10), tf32r(p11));
        }
        ls0 += __shfl_xor_sync(0xffffffffu, ls0, 1);
        ls0 += __shfl_xor_sync(0xffffffffu, ls0, 2);
        ls1 += __shfl_xor_sync(0xffffffffu, ls1, 1);
        ls1 += __shfl_xor_sync(0xffffffffu, ls1, 2);
        l0 = l0 * cf0 + ls0;
        l1 = l1 * cf1 + ls1;

#pragma unroll
        for (int nf = 0; nf < 8; nf++) {
            oacc[nf][0] *= cf0; oacc[nf][1] *= cf0;
            oacc[nf][2] *= cf1; oacc[nf][3] *= cf1;
        }
        __syncwarp();

        // ---- O += P V^T : per-warp m16 x n64 x k128 ----
#pragma unroll
        for (int ks = 0; ks < 16; ks++) {
            const float* p0 = Ps + (rbase + g) * 132 + ks * 8 + c4;
            const float* p1 = Ps + (rbase + g + 8) * 132 + ks * 8 + c4;
            uint32_t a0 = fu(p0[0]), a1 = fu(p1[0]);
            uint32_t a2 = fu(p0[4]), a3 = fu(p1[4]);
#pragma unroll
            for (int nf = 0; nf < 8; nf++) {
                const float* vp = Vs + (nf * 8 + g) * 132 + ks * 8 + c4;
                uint32_t b0 = fu(vp[0]), b1 = fu(vp[4]);
                MMA_TF32(oacc[nf], a0, a1, a2, a3, b0, b1);
            }
        }
    }

    // ---- normalize ----
    float inv0 = 1.0f / l0, inv1 = 1.0f / l1;
#pragma unroll
    for (int nf = 0; nf < 8; nf++) {
        oacc[nf][0] *= inv0; oacc[nf][1] *= inv0;
        oacc[nf][2] *= inv1; oacc[nf][3] *= inv1;
    }
    __syncthreads();   // everyone done with Vs/Ps as attention operands

    // write O -> Ps as [tq][c] (tf32), and Wo -> Ks as [o][c] (tf32)
    {
        float* or0 = Ps + (rbase + g) * 132;
        float* or1 = Ps + (rbase + g + 8) * 132;
#pragma unroll
        for (int nf = 0; nf < 8; nf++) {
            *(float2*)(or0 + nf * 8 + 2 * c4) =
                make_float2(tf32r(oacc[nf][0]), tf32r(oacc[nf][1]));
            *(float2*)(or1 + nf * 8 + 2 * c4) =
                make_float2(tf32r(oacc[nf][2]), tf32r(oacc[nf][3]));
        }
    }
#pragma unroll
    for (int it = 0; it < 4; it++) {
        int flat = it * 1024 + tid * 4;
        float4 w = *(const float4*)(Wo + flat);
        w.x = tf32r(w.x); w.y = tf32r(w.y); w.z = tf32r(w.z); w.w = tf32r(w.w);
        *(float4*)(Ks + (flat >> 6) * 68 + (flat & 63)) = w;
    }
    __syncthreads();

    // ---- projection: P2[tq][o] = sum_c O[tq][c] * Wo[o][c] ----
    float pacc[8][4];
#pragma unroll
    for (int i = 0; i < 8; i++)
#pragma unroll
        for (int k = 0; k < 4; k++) pacc[i][k] = 0.f;

#pragma unroll
    for (int ks = 0; ks < 8; ks++) {
        const float* o0 = Ps + (rbase + g) * 132 + ks * 8 + c4;
        const float* o1 = Ps + (rbase + g + 8) * 132 + ks * 8 + c4;
        uint32_t a0 = fu(o0[0]), a1 = fu(o1[0]);
        uint32_t a2 = fu(o0[4]), a3 = fu(o1[4]);
#pragma unroll
        for (int nf = 0; nf < 8; nf++) {
            const float* wp = Ks + (nf * 8 + g) * 68 + ks * 8 + c4;
            uint32_t b0 = fu(wp[0]), b1 = fu(wp[4]);
            MMA_TF32(pacc[nf], a0, a1, a2, a3, b0, b1);
        }
    }
    __syncthreads();

    // transpose result into Vs region as [o][tq]
#pragma unroll
    for (int nf = 0; nf < 8; nf++) {
        int o0 = nf * 8 + 2 * c4;
        Vs[o0 * 132 + rbase + g]           = pacc[nf][0];
        Vs[(o0 + 1) * 132 + rbase + g]     = pacc[nf][1];
        Vs[o0 * 132 + rbase + g + 8]       = pacc[nf][2];
        Vs[(o0 + 1) * 132 + rbase + g + 8] = pacc[nf][3];
    }
    __syncthreads();

    // final: out[o][t] = proj + x (residual), coalesced
    const float* xb = x + (size_t)n * C * T + j * TILE;
    float* ob = out + (size_t)n * C * T + j * TILE;
#pragma unroll
    for (int it = 0; it < 8; it++) {
        int flat = it * 1024 + tid * 4;
        int o = flat >> 7, t = flat & 127;
        float4 v  = *(const float4*)(Vs + o * 132 + t);
        float4 xr = *(const float4*)(xb + o * T + t);
        float4 r  = make_float4(v.x + xr.x, v.y + xr.y, v.z + xr.z, v.w + xr.w);
        *(float4*)(ob + o * T + t) = r;
    }
}

// ---------------------------------------------------------------------------
extern "C" void kernel_launch(void* const* d_in, const int* in_sizes, int n_in,
                              void* d_out, int out_size)
{
    const float* x     = (const float*)d_in[0];
    const float* Wq    = (const float*)d_in[1];
    const float* Wk    = (const float*)d_in[2];
    const float* Wv    = (const float*)d_in[3];
    const float* Wo    = (const float*)d_in[4];
    const float* scale = (const float*)d_in[5];
    float* out = (float*)d_out;

    const int smem1 = (64 * 128 + 3 * 64 * 64) * 4;                    // 81920 B
    const int smem2 = (8704 + 8704 + 8448 + 16896) * 4;                // 171008 B
    cudaFuncSetAttribute(qkv_kernel,  cudaFuncAttributeMaxDynamicSharedMemorySize, smem1);
    cudaFuncSetAttribute(attn_kernel, cudaFuncAttributeMaxDynamicSharedMemorySize, smem2);

    dim3 grid(8, 128);
    qkv_kernel<<<grid, 256, smem1>>>(x, Wq, Wk, Wv, scale);
    attn_kernel<<<grid, 256, smem2>>>(x, Wo, out);
}

// round 4
// speedup vs baseline: 4.3509x; 1.4640x over previous
#include <cuda_runtime.h>
#include <cuda_bf16.h>
#include <cstdint>

#define NB 128
#define C 64
#define T 1024
#define TILE 128
#define NTILE 8

// bf16 scratch: Q,K t-major [n][t][c] (Q has scale*log2e folded), V [n][c][t].
__device__ __nv_bfloat16 g_Qb[NB * T * C];
__device__ __nv_bfloat16 g_Kb[NB * T * C];
__device__ __nv_bfloat16 g_Vb[NB * C * T];

__device__ __forceinline__ float ex2a(float x) {
    float y;
    asm("ex2.approx.ftz.f32 %0, %1;" : "=f"(y) : "f"(x));
    return y;
}
__device__ __forceinline__ uint32_t packbf(float lo, float hi) {
    __nv_bfloat162 v = __floats2bfloat162_rn(lo, hi);
    return *(uint32_t*)&v;
}
__device__ __forceinline__ uint32_t ldu32(const __nv_bfloat16* p) {
    return *(const uint32_t*)p;
}

#define MMA_BF16(d, a0, a1, a2, a3, b0, b1)                                   \
    asm volatile(                                                             \
        "mma.sync.aligned.m16n8k16.row.col.f32.bf16.bf16.f32 "                \
        "{%0,%1,%2,%3}, {%4,%5,%6,%7}, {%8,%9}, {%0,%1,%2,%3};"               \
        : "+f"(d[0]), "+f"(d[1]), "+f"(d[2]), "+f"(d[3])                      \
        : "r"(a0), "r"(a1), "r"(a2), "r"(a3), "r"(b0), "r"(b1))

// ---------------------------------------------------------------------------
// Kernel 1: QKV projection via bf16 mma.sync. grid (8,128), 256 threads.
// smem (bf16): xT [128][72], Ws 3x[64][72], Vst [64][136]
// ---------------------------------------------------------------------------
#define XT_O  0
#define WS_O  9216
#define VST_O (9216 + 13824)
#define QKV_SMEM_BF (VST_O + 8704)     // 31744 bf16 = 63488 B

extern "C" __global__ void __launch_bounds__(256)
qkv_kernel(const float* __restrict__ x,
           const float* __restrict__ Wq,
           const float* __restrict__ Wk,
           const float* __restrict__ Wv,
           const float* __restrict__ scale_p)
{
    extern __shared__ __nv_bfloat16 smb[];
    __nv_bfloat16* xT  = smb + XT_O;
    __nv_bfloat16* Ws  = smb + WS_O;
    __nv_bfloat16* Vst = smb + VST_O;

    const int j = blockIdx.x, n = blockIdx.y;
    const int tid = threadIdx.x;
    const int warp = tid >> 5, lane = tid & 31;
    const int g = lane >> 2, c4 = lane & 3;
    const int rb = warp * 16;
    const float qs = scale_p[0] * 1.44269504088896f;

    // x [c][t] fp32 -> xT [t][c] bf16
    const float* xb = x + (size_t)n * C * T + j * TILE;
    for (int idx = tid; idx < 8192; idx += 256) {
        int c = idx >> 7, t = idx & 127;
        xT[t * 72 + c] = __float2bfloat16(xb[c * T + t]);
    }
    // weights [o][c] fp32 -> bf16, stride 72
    for (int idx = tid; idx < 4096; idx += 256) {
        int o = idx >> 6, c = idx & 63;
        Ws[o * 72 + c]            = __float2bfloat16(Wq[idx]);
        Ws[4608 + o * 72 + c]     = __float2bfloat16(Wk[idx]);
        Ws[2 * 4608 + o * 72 + c] = __float2bfloat16(Wv[idx]);
    }
    __syncthreads();

    for (int m = 0; m < 3; m++) {
        float acc[8][4];
#pragma unroll
        for (int i = 0; i < 8; i++)
#pragma unroll
            for (int k = 0; k < 4; k++) acc[i][k] = 0.f;

        const __nv_bfloat16* Wm = Ws + m * 4608;
#pragma unroll
        for (int ks = 0; ks < 4; ks++) {
            int co = ks * 16 + 2 * c4;
            uint32_t a0 = ldu32(&xT[(rb + g) * 72 + co]);
            uint32_t a1 = ldu32(&xT[(rb + g + 8) * 72 + co]);
            uint32_t a2 = ldu32(&xT[(rb + g) * 72 + co + 8]);
            uint32_t a3 = ldu32(&xT[(rb + g + 8) * 72 + co + 8]);
#pragma unroll
            for (int nf = 0; nf < 8; nf++) {
                uint32_t b0 = ldu32(&Wm[(nf * 8 + g) * 72 + co]);
                uint32_t b1 = ldu32(&Wm[(nf * 8 + g) * 72 + co + 8]);
                MMA_BF16(acc[nf], a0, a1, a2, a3, b0, b1);
            }
        }

        if (m == 0) {
#pragma unroll
            for (int i = 0; i < 8; i++)
#pragma unroll
                for (int k = 0; k < 4; k++) acc[i][k] *= qs;
        }

        if (m < 2) {
            __nv_bfloat16* dst = (m == 0 ? g_Qb : g_Kb) + ((size_t)n * T + j * TILE) * C;
            int r0 = rb + g, r1 = rb + g + 8;
#pragma unroll
            for (int nf = 0; nf < 8; nf++) {
                int o = nf * 8 + 2 * c4;
                *(uint32_t*)&dst[r0 * 64 + o] = packbf(acc[nf][0], acc[nf][1]);
                *(uint32_t*)&dst[r1 * 64 + o] = packbf(acc[nf][2], acc[nf][3]);
            }
        } else {
            int r0 = rb + g, r1 = rb + g + 8;
#pragma unroll
            for (int nf = 0; nf < 8; nf++) {
                int o = nf * 8 + 2 * c4;
                Vst[o * 136 + r0]       = __float2bfloat16(acc[nf][0]);
                Vst[(o + 1) * 136 + r0] = __float2bfloat16(acc[nf][1]);
                Vst[o * 136 + r1]       = __float2bfloat16(acc[nf][2]);
                Vst[(o + 1) * 136 + r1] = __float2bfloat16(acc[nf][3]);
            }
        }
    }
    __syncthreads();

    // Vst [c][t] -> g_Vb, coalesced float4 (8 bf16) chunks
    __nv_bfloat16* vdst = g_Vb + (size_t)n * C * T + j * TILE;
#pragma unroll
    for (int it = 0; it < 4; it++) {
        int flat = it * 2048 + tid * 8;       // bf16 units
        int r = flat >> 7, t = flat & 127;
        float4 v = *(const float4*)&Vst[r * 136 + t];
        *(float4*)&vdst[r * T + t] = v;
    }
}

// ---------------------------------------------------------------------------
// Kernel 2: attention, bf16 mma.sync, no-max softmax, fused Wo + residual.
// grid (8,128), 256 threads, 2 CTAs/SM.
// smem (bf16 units): Qs[128][72]  Ks[128][72]  Vs[64][136]  Ps[128][136]
// ---------------------------------------------------------------------------
#define AQS_O 0
#define AKS_O 9216
#define AVS_O 18432
#define APS_O 27136
#define ATTN_SMEM_BF (APS_O + 17408)   // 44544 bf16 = 89088 B

extern "C" __global__ void __launch_bounds__(256, 2)
attn_kernel(const float* __restrict__ x,
            const float* __restrict__ Wo,
            float* __restrict__ out)
{
    extern __shared__ __nv_bfloat16 smb[];
    __nv_bfloat16* Qs = smb + AQS_O;
    __nv_bfloat16* Ks = smb + AKS_O;
    __nv_bfloat16* Vs = smb + AVS_O;
    __nv_bfloat16* Ps = smb + APS_O;

    const int j = blockIdx.x, n = blockIdx.y;
    const int tid = threadIdx.x;
    const int warp = tid >> 5, lane = tid & 31;
    const int g = lane >> 2, c4 = lane & 3;
    const int rb = warp * 16;

    // load Q tile [128][64] bf16 -> stride 72
    const __nv_bfloat16* qsrc = g_Qb + ((size_t)n * T + j * TILE) * C;
#pragma unroll
    for (int it = 0; it < 4; it++) {
        int flat = it * 2048 + tid * 8;
        int r = flat >> 6, c = flat & 63;
        float4 v = *(const float4*)&qsrc[flat];
        *(float4*)&Qs[r * 72 + c] = v;
    }

    const __nv_bfloat16* kbase = g_Kb + (size_t)n * T * C;
    const __nv_bfloat16* vbase = g_Vb + (size_t)n * C * T;

    float l0 = 0.f, l1 = 0.f;
    float oacc[8][4];
#pragma unroll
    for (int i = 0; i < 8; i++)
#pragma unroll
        for (int k = 0; k < 4; k++) oacc[i][k] = 0.f;

    for (int st = 0; st < NTILE; st++) {
        __syncthreads();   // prev PV done; safe to overwrite Ks/Vs
        const __nv_bfloat16* ks = kbase + (size_t)st * TILE * C;
#pragma unroll
        for (int it = 0; it < 4; it++) {
            int flat = it * 2048 + tid * 8;
            int r = flat >> 6, c = flat & 63;
            float4 v = *(const float4*)&ks[flat];
            *(float4*)&Ks[r * 72 + c] = v;
        }
        const __nv_bfloat16* vs = vbase + st * TILE;
#pragma unroll
        for (int it = 0; it < 4; it++) {
            int flat = it * 2048 + tid * 8;
            int r = flat >> 7, t = flat & 127;
            float4 v = *(const float4*)&vs[r * T + t];
            *(float4*)&Vs[r * 136 + t] = v;
        }
        __syncthreads();

        // S = Q K^T in two 64-col halves; P = exp2(S) (scale folded in Q)
#pragma unroll
        for (int hn = 0; hn < 2; hn++) {
            float sacc[8][4];
#pragma unroll
            for (int i = 0; i < 8; i++)
#pragma unroll
                for (int k = 0; k < 4; k++) sacc[i][k] = 0.f;

#pragma unroll
            for (int ks4 = 0; ks4 < 4; ks4++) {
                int co = ks4 * 16 + 2 * c4;
                uint32_t a0 = ldu32(&Qs[(rb + g) * 72 + co]);
                uint32_t a1 = ldu32(&Qs[(rb + g + 8) * 72 + co]);
                uint32_t a2 = ldu32(&Qs[(rb + g) * 72 + co + 8]);
                uint32_t a3 = ldu32(&Qs[(rb + g + 8) * 72 + co + 8]);
#pragma unroll
                for (int nf = 0; nf < 8; nf++) {
                    int tk = hn * 64 + nf * 8 + g;
                    uint32_t b0 = ldu32(&Ks[tk * 72 + co]);
                    uint32_t b1 = ldu32(&Ks[tk * 72 + co + 8]);
                    MMA_BF16(sacc[nf], a0, a1, a2, a3, b0, b1);
                }
            }
            int r0 = rb + g, r1 = rb + g + 8;
#pragma unroll
            for (int nf = 0; nf < 8; nf++) {
                int col = hn * 64 + nf * 8 + 2 * c4;
                float e0 = ex2a(sacc[nf][0]);
                float e1 = ex2a(sacc[nf][1]);
                float e2 = ex2a(sacc[nf][2]);
                float e3 = ex2a(sacc[nf][3]);
                l0 += e0 + e1;
                l1 += e2 + e3;
                *(uint32_t*)&Ps[r0 * 136 + col] = packbf(e0, e1);
                *(uint32_t*)&Ps[r1 * 136 + col] = packbf(e2, e3);
            }
        }
        __syncthreads();

        // O += P V^T : m16 n64 k128
#pragma unroll
        for (int ks8 = 0; ks8 < 8; ks8++) {
            int so = ks8 * 16 + 2 * c4;
            uint32_t a0 = ldu32(&Ps[(rb + g) * 136 + so]);
            uint32_t a1 = ldu32(&Ps[(rb + g + 8) * 136 + so]);
            uint32_t a2 = ldu32(&Ps[(rb + g) * 136 + so + 8]);
            uint32_t a3 = ldu32(&Ps[(rb + g + 8) * 136 + so + 8]);
#pragma unroll
            for (int nf = 0; nf < 8; nf++) {
                uint32_t b0 = ldu32(&Vs[(nf * 8 + g) * 136 + so]);
                uint32_t b1 = ldu32(&Vs[(nf * 8 + g) * 136 + so + 8]);
                MMA_BF16(oacc[nf], a0, a1, a2, a3, b0, b1);
            }
        }
    }

    // row sums -> normalize
    l0 += __shfl_xor_sync(0xffffffffu, l0, 1);
    l0 += __shfl_xor_sync(0xffffffffu, l0, 2);
    l1 += __shfl_xor_sync(0xffffffffu, l1, 1);
    l1 += __shfl_xor_sync(0xffffffffu, l1, 2);
    float inv0 = 1.0f / l0, inv1 = 1.0f / l1;

    // O (bf16) -> Qs (reuse) as [tq][c] stride 72
    {
        int r0 = rb + g, r1 = rb + g + 8;
#pragma unroll
        for (int nf = 0; nf < 8; nf++) {
            int o = nf * 8 + 2 * c4;
            *(uint32_t*)&Qs[r0 * 72 + o] = packbf(oacc[nf][0] * inv0, oacc[nf][1] * inv0);
            *(uint32_t*)&Qs[r1 * 72 + o] = packbf(oacc[nf][2] * inv1, oacc[nf][3] * inv1);
        }
    }
    // Wo -> Ks (reuse) as [o][c] bf16 stride 72
#pragma unroll
    for (int it = 0; it < 4; it++) {
        int flat = it * 1024 + tid * 4;
        int o = flat >> 6, c = flat & 63;
        float4 w = *(const float4*)&Wo[flat];
        *(uint32_t*)&Ks[o * 72 + c]     = packbf(w.x, w.y);
        *(uint32_t*)&Ks[o * 72 + c + 2] = packbf(w.z, w.w);
    }
    __syncthreads();

    // D2 = O * Wo^T : m16 n64 k64
    float pacc[8][4];
#pragma unroll
    for (int i = 0; i < 8; i++)
#pragma unroll
        for (int k = 0; k < 4; k++) pacc[i][k] = 0.f;

#pragma unroll
    for (int ks4 = 0; ks4 < 4; ks4++) {
        int co = ks4 * 16 + 2 * c4;
        uint32_t a0 = ldu32(&Qs[(rb + g) * 72 + co]);
        uint32_t a1 = ldu32(&Qs[(rb + g + 8) * 72 + co]);
        uint32_t a2 = ldu32(&Qs[(rb + g) * 72 + co + 8]);
        uint32_t a3 = ldu32(&Qs[(rb + g + 8) * 72 + co + 8]);
#pragma unroll
        for (int nf = 0; nf < 8; nf++) {
            uint32_t b0 = ldu32(&Ks[(nf * 8 + g) * 72 + co]);
            uint32_t b1 = ldu32(&Ks[(nf * 8 + g) * 72 + co + 8]);
            MMA_BF16(pacc[nf], a0, a1, a2, a3, b0, b1);
        }
    }

    // stage transposed into Ps region as fp32 [o][t] stride 132
    float* Pf = (float*)(smb + APS_O);
    {
        int r0 = rb + g, r1 = rb + g + 8;
#pragma unroll
        for (int nf = 0; nf < 8; nf++) {
            int o = nf * 8 + 2 * c4;
            Pf[o * 132 + r0]       = pacc[nf][0];
            Pf[(o + 1) * 132 + r0] = pacc[nf][1];
            Pf[o * 132 + r1]       = pacc[nf][2];
            Pf[(o + 1) * 132 + r1] = pacc[nf][3];
        }
    }
    __syncthreads();

    // out[o][t] = proj + x, coalesced float4
    const float* xb = x + (size_t)n * C * T + j * TILE;
    float* ob = out + (size_t)n * C * T + j * TILE;
#pragma unroll
    for (int it = 0; it < 8; it++) {
        int flat = it * 1024 + tid * 4;
        int o = flat >> 7, t = flat & 127;
        float4 v  = *(const float4*)&Pf[o * 132 + t];
        float4 xr = *(const float4*)&xb[o * T + t];
        float4 r  = make_float4(v.x + xr.x, v.y + xr.y, v.z + xr.z, v.w + xr.w);
        *(float4*)&ob[o * T + t] = r;
    }
}

// ---------------------------------------------------------------------------
extern "C" void kernel_launch(void* const* d_in, const int* in_sizes, int n_in,
                              void* d_out, int out_size)
{
    const float* x     = (const float*)d_in[0];
    const float* Wq    = (const float*)d_in[1];
    const float* Wk    = (const float*)d_in[2];
    const float* Wv    = (const float*)d_in[3];
    const float* Wo    = (const float*)d_in[4];
    const float* scale = (const float*)d_in[5];
    float* out = (float*)d_out;

    const int smem1 = QKV_SMEM_BF * 2;     // 63488 B
    const int smem2 = ATTN_SMEM_BF * 2;    // 89088 B
    cudaFuncSetAttribute(qkv_kernel,  cudaFuncAttributeMaxDynamicSharedMemorySize, smem1);
    cudaFuncSetAttribute(attn_kernel, cudaFuncAttributeMaxDynamicSharedMemorySize, smem2);

    dim3 grid(8, 128);
    qkv_kernel<<<grid, 256, smem1>>>(x, Wq, Wk, Wv, scale);
    attn_kernel<<<grid, 256, smem2>>>(x, Wo, out);
}

// round 7
// speedup vs baseline: 7.5376x; 1.7324x over previous
#include <cuda_runtime.h>
#include <cuda_bf16.h>
#include <cstdint>

#define NB 128
#define C 64
#define T 1024
#define TILE 128
#define NTILE 8

// bf16 scratch: Q,K t-major [n][t][c] (Q has scale*log2e folded), V [n][c][t].
__device__ __nv_bfloat16 g_Qb[NB * T * C];
__device__ __nv_bfloat16 g_Kb[NB * T * C];
__device__ __nv_bfloat16 g_Vb[NB * C * T];

__device__ __forceinline__ float ex2a(float x) {
    float y;
    asm("ex2.approx.ftz.f32 %0, %1;" : "=f"(y) : "f"(x));
    return y;
}
__device__ __forceinline__ uint32_t packbf(float lo, float hi) {
    __nv_bfloat162 v = __floats2bfloat162_rn(lo, hi);
    return *(uint32_t*)&v;
}
__device__ __forceinline__ uint32_t ldu32(const __nv_bfloat16* p) {
    return *(const uint32_t*)p;
}
__device__ __forceinline__ uint32_t smaddr(const void* p) {
    uint32_t a;
    asm("{ .reg .u64 t; cvta.to.shared.u64 t, %1; cvt.u32.u64 %0, t; }" : "=r"(a) : "l"(p));
    return a;
}

#define MMA_BF16(d, a0, a1, a2, a3, b0, b1)                                   \
    asm volatile(                                                             \
        "mma.sync.aligned.m16n8k16.row.col.f32.bf16.bf16.f32 "                \
        "{%0,%1,%2,%3}, {%4,%5,%6,%7}, {%8,%9}, {%0,%1,%2,%3};"               \
        : "+f"(d[0]), "+f"(d[1]), "+f"(d[2]), "+f"(d[3])                      \
        : "r"(a0), "r"(a1), "r"(a2), "r"(a3), "r"(b0), "r"(b1))

#define LDSM4(R, a)                                                           \
    asm volatile("ldmatrix.sync.aligned.m8n8.x4.shared.b16 {%0,%1,%2,%3}, [%4];" \
        : "=r"((R)[0]), "=r"((R)[1]), "=r"((R)[2]), "=r"((R)[3]) : "r"(a))

// ---------------------------------------------------------------------------
// Kernel 1: QKV projection via bf16 mma.sync. 256 thr.
// ---------------------------------------------------------------------------
#define XT_O  0
#define WS_O  9216
#define VST_O (9216 + 13824)
#define QKV_SMEM_BF (VST_O + 8704)     // 31744 bf16 = 63488 B

extern "C" __global__ void __launch_bounds__(256)
qkv_kernel(const float* __restrict__ x,
           const float* __restrict__ Wq,
           const float* __restrict__ Wk,
           const float* __restrict__ Wv,
           const float* __restrict__ scale_p)
{
    extern __shared__ __nv_bfloat16 smb[];
    __nv_bfloat16* xT  = smb + XT_O;
    __nv_bfloat16* Ws  = smb + WS_O;
    __nv_bfloat16* Vst = smb + VST_O;

    const int j = blockIdx.x, n = blockIdx.y;
    const int tid = threadIdx.x;
    const int warp = tid >> 5, lane = tid & 31;
    const int g = lane >> 2, c4 = lane & 3;
    const int rb = warp * 16;
    const float qs = scale_p[0] * 1.44269504088896f;

    const float* xb = x + (size_t)n * C * T + j * TILE;
    for (int idx = tid; idx < 8192; idx += 256) {
        int c = idx >> 7, t = idx & 127;
        xT[t * 72 + c] = __float2bfloat16(xb[c * T + t]);
    }
    for (int idx = tid; idx < 4096; idx += 256) {
        int o = idx >> 6, c = idx & 63;
        Ws[o * 72 + c]            = __float2bfloat16(Wq[idx]);
        Ws[4608 + o * 72 + c]     = __float2bfloat16(Wk[idx]);
        Ws[2 * 4608 + o * 72 + c] = __float2bfloat16(Wv[idx]);
    }
    __syncthreads();

    for (int m = 0; m < 3; m++) {
        float acc[8][4];
#pragma unroll
        for (int i = 0; i < 8; i++)
#pragma unroll
            for (int k = 0; k < 4; k++) acc[i][k] = 0.f;

        const __nv_bfloat16* Wm = Ws + m * 4608;
#pragma unroll
        for (int ks = 0; ks < 4; ks++) {
            int co = ks * 16 + 2 * c4;
            uint32_t a0 = ldu32(&xT[(rb + g) * 72 + co]);
            uint32_t a1 = ldu32(&xT[(rb + g + 8) * 72 + co]);
            uint32_t a2 = ldu32(&xT[(rb + g) * 72 + co + 8]);
            uint32_t a3 = ldu32(&xT[(rb + g + 8) * 72 + co + 8]);
#pragma unroll
            for (int nf = 0; nf < 8; nf++) {
                uint32_t b0 = ldu32(&Wm[(nf * 8 + g) * 72 + co]);
                uint32_t b1 = ldu32(&Wm[(nf * 8 + g) * 72 + co + 8]);
                MMA_BF16(acc[nf], a0, a1, a2, a3, b0, b1);
            }
        }

        if (m == 0) {
#pragma unroll
            for (int i = 0; i < 8; i++)
#pragma unroll
                for (int k = 0; k < 4; k++) acc[i][k] *= qs;
        }

        if (m < 2) {
            __nv_bfloat16* dst = (m == 0 ? g_Qb : g_Kb) + ((size_t)n * T + j * TILE) * C;
            int r0 = rb + g, r1 = rb + g + 8;
#pragma unroll
            for (int nf = 0; nf < 8; nf++) {
                int o = nf * 8 + 2 * c4;
                *(uint32_t*)&dst[r0 * 64 + o] = packbf(acc[nf][0], acc[nf][1]);
                *(uint32_t*)&dst[r1 * 64 + o] = packbf(acc[nf][2], acc[nf][3]);
            }
        } else {
            int r0 = rb + g, r1 = rb + g + 8;
#pragma unroll
            for (int nf = 0; nf < 8; nf++) {
                int o = nf * 8 + 2 * c4;
                Vst[o * 136 + r0]       = __float2bfloat16(acc[nf][0]);
                Vst[(o + 1) * 136 + r0] = __float2bfloat16(acc[nf][1]);
                Vst[o * 136 + r1]       = __float2bfloat16(acc[nf][2]);
                Vst[(o + 1) * 136 + r1] = __float2bfloat16(acc[nf][3]);
            }
        }
    }
    __syncthreads();

    __nv_bfloat16* vdst = g_Vb + (size_t)n * C * T + j * TILE;
#pragma unroll
    for (int it = 0; it < 4; it++) {
        int flat = it * 2048 + tid * 8;
        int r = flat >> 7, t = flat & 127;
        float4 v = *(const float4*)&Vst[r * 136 + t];
        *(float4*)&vdst[r * T + t] = v;
    }
}

// ---------------------------------------------------------------------------
// Kernel 2: attention. 128 threads (4 warps x m32), ldmatrix fragments,
// 2 CTAs/SM. smem: Qs[128][72] Ks[128][72] Vs[64][136] Ps[128][136] bf16.
// ---------------------------------------------------------------------------
#define AQS_O 0
#define AKS_O 9216
#define AVS_O 18432
#define APS_O 27136
#define ATTN_SMEM_BF (APS_O + 17408)   // 44544 bf16 = 89088 B

extern "C" __global__ void __launch_bounds__(128, 2)
attn_kernel(const float* __restrict__ x,
            const float* __restrict__ Wo,
            float* __restrict__ out)
{
    extern __shared__ __nv_bfloat16 smb[];
    __nv_bfloat16* Qs = smb + AQS_O;
    __nv_bfloat16* Ks = smb + AKS_O;
    __nv_bfloat16* Vs = smb + AVS_O;
    __nv_bfloat16* Ps = smb + APS_O;

    const int j = blockIdx.x, n = blockIdx.y;
    const int tid = threadIdx.x;
    const int warp = tid >> 5, lane = tid & 31;
    const int g = lane >> 2, c4 = lane & 3;
    const int rb = warp * 32;

    // ldmatrix lane roles
    const int arow = ((lane >> 3) & 1) * 8 + (lane & 7);  // A: row offset
    const int acol = (lane >> 4) * 8;                     // A: col offset
    const int brow = (lane >> 4) * 8 + (lane & 7);        // B: row offset
    const int bcol = ((lane >> 3) & 1) * 8;               // B: col offset

    const uint32_t sQ = smaddr(Qs);
    const uint32_t sK = smaddr(Ks);
    const uint32_t sV = smaddr(Vs);
    const uint32_t sP = smaddr(Ps);

    // load Q tile [128][64] bf16 -> stride 72
    const __nv_bfloat16* qsrc = g_Qb + ((size_t)n * T + j * TILE) * C;
#pragma unroll
    for (int it = 0; it < 8; it++) {
        int flat = it * 1024 + tid * 8;
        int r = flat >> 6, c = flat & 63;
        float4 v = *(const float4*)&qsrc[flat];
        *(float4*)&Qs[r * 72 + c] = v;
    }

    const __nv_bfloat16* kbase = g_Kb + (size_t)n * T * C;
    const __nv_bfloat16* vbase = g_Vb + (size_t)n * C * T;

    float lsum[2][2] = {{0.f, 0.f}, {0.f, 0.f}};
    float oacc[2][8][4];
#pragma unroll
    for (int mb = 0; mb < 2; mb++)
#pragma unroll
        for (int i = 0; i < 8; i++)
#pragma unroll
            for (int k = 0; k < 4; k++) oacc[mb][i][k] = 0.f;

    const uint32_t aQ0 = sQ + ((rb + arow) * 72 + acol) * 2;
    const uint32_t aQ1 = aQ0 + 16 * 72 * 2;
    const uint32_t aP0 = sP + ((rb + arow) * 136 + acol) * 2;
    const uint32_t aP1 = aP0 + 16 * 136 * 2;

    for (int st = 0; st < NTILE; st++) {
        __syncthreads();   // prev PV done; safe to overwrite Ks/Vs
        const __nv_bfloat16* ks = kbase + (size_t)st * TILE * C;
#pragma unroll
        for (int it = 0; it < 8; it++) {
            int flat = it * 1024 + tid * 8;
            int r = flat >> 6, c = flat & 63;
            float4 v = *(const float4*)&ks[flat];
            *(float4*)&Ks[r * 72 + c] = v;
        }
        const __nv_bfloat16* vs = vbase + st * TILE;
#pragma unroll
        for (int it = 0; it < 8; it++) {
            int flat = it * 1024 + tid * 8;
            int r = flat >> 7, t = flat & 127;
            float4 v = *(const float4*)&vs[r * T + t];
            *(float4*)&Vs[r * 136 + t] = v;
        }
        __syncthreads();

        // S = Q K^T in two 64-col halves; P = exp2(S)
#pragma unroll
        for (int hn = 0; hn < 2; hn++) {
            float sacc[2][8][4];
#pragma unroll
            for (int mb = 0; mb < 2; mb++)
#pragma unroll
                for (int i = 0; i < 8; i++)
#pragma unroll
                    for (int k = 0; k < 4; k++) sacc[mb][i][k] = 0.f;

#pragma unroll
            for (int ks4 = 0; ks4 < 4; ks4++) {
                uint32_t A0[4], A1[4];
                LDSM4(A0, aQ0 + ks4 * 32);
                LDSM4(A1, aQ1 + ks4 * 32);
#pragma unroll
                for (int nf2 = 0; nf2 < 4; nf2++) {
                    uint32_t Bv[4];
                    LDSM4(Bv, sK + ((hn * 64 + nf2 * 16 + brow) * 72 +
                                    bcol + ks4 * 16) * 2);
                    MMA_BF16(sacc[0][nf2 * 2],     A0[0], A0[1], A0[2], A0[3], Bv[0], Bv[1]);
                    MMA_BF16(sacc[1][nf2 * 2],     A1[0], A1[1], A1[2], A1[3], Bv[0], Bv[1]);
                    MMA_BF16(sacc[0][nf2 * 2 + 1], A0[0], A0[1], A0[2], A0[3], Bv[2], Bv[3]);
                    MMA_BF16(sacc[1][nf2 * 2 + 1], A1[0], A1[1], A1[2], A1[3], Bv[2], Bv[3]);
                }
            }
#pragma unroll
            for (int mb = 0; mb < 2; mb++) {
                int r0 = rb + mb * 16 + g, r1 = r0 + 8;
#pragma unroll
                for (int nf = 0; nf < 8; nf++) {
                    int col = hn * 64 + nf * 8 + 2 * c4;
                    float e0 = ex2a(sacc[mb][nf][0]);
                    float e1 = ex2a(sacc[mb][nf][1]);
                    float e2 = ex2a(sacc[mb][nf][2]);
                    float e3 = ex2a(sacc[mb][nf][3]);
                    lsum[mb][0] += e0 + e1;
                    lsum[mb][1] += e2 + e3;
                    *(uint32_t*)&Ps[r0 * 136 + col] = packbf(e0, e1);
                    *(uint32_t*)&Ps[r1 * 136 + col] = packbf(e2, e3);
                }
            }
        }
        __syncwarp();   // P rows are warp-private: warp-level sync suffices

        // O += P V^T : m32 n64 k128
#pragma unroll
        for (int ks8 = 0; ks8 < 8; ks8++) {
            uint32_t A0[4], A1[4];
            LDSM4(A0, aP0 + ks8 * 32);
            LDSM4(A1, aP1 + ks8 * 32);
#pragma unroll
            for (int nf2 = 0; nf2 < 4; nf2++) {
                uint32_t Bv[4];
                LDSM4(Bv, sV + ((nf2 * 16 + brow) * 136 + bcol + ks8 * 16) * 2);
                MMA_BF16(oacc[0][nf2 * 2],     A0[0], A0[1], A0[2], A0[3], Bv[0], Bv[1]);
                MMA_BF16(oacc[1][nf2 * 2],     A1[0], A1[1], A1[2], A1[3], Bv[0], Bv[1]);
                MMA_BF16(oacc[0][nf2 * 2 + 1], A0[0], A0[1], A0[2], A0[3], Bv[2], Bv[3]);
                MMA_BF16(oacc[1][nf2 * 2 + 1], A1[0], A1[1], A1[2], A1[3], Bv[2], Bv[3]);
            }
        }
    }

    // row sums -> normalize
#pragma unroll
    for (int mb = 0; mb < 2; mb++)
#pragma unroll
        for (int h = 0; h < 2; h++) {
            lsum[mb][h] += __shfl_xor_sync(0xffffffffu, lsum[mb][h], 1);
            lsum[mb][h] += __shfl_xor_sync(0xffffffffu, lsum[mb][h], 2);
        }
    float inv00 = 1.0f / lsum[0][0], inv01 = 1.0f / lsum[0][1];
    float inv10 = 1.0f / lsum[1][0], inv11 = 1.0f / lsum[1][1];

    // O (bf16, normalized) -> Qs (own rows) as [tq][c] stride 72
#pragma unroll
    for (int mb = 0; mb < 2; mb++) {
        int r0 = rb + mb * 16 + g, r1 = r0 + 8;
        float i0 = mb ? inv10 : inv00, i1 = mb ? inv11 : inv01;
#pragma unroll
        for (int nf = 0; nf < 8; nf++) {
            int o = nf * 8 + 2 * c4;
            *(uint32_t*)&Qs[r0 * 72 + o] = packbf(oacc[mb][nf][0] * i0, oacc[mb][nf][1] * i0);
            *(uint32_t*)&Qs[r1 * 72 + o] = packbf(oacc[mb][nf][2] * i1, oacc[mb][nf][3] * i1);
        }
    }
    __syncthreads();   // everyone past last S-phase reads of Ks / PV reads of Ps

    // Wo -> Ks as [o][c] bf16 stride 72
#pragma unroll
    for (int it = 0; it < 8; it++) {
        int flat = it * 512 + tid * 4;
        int o = flat >> 6, c = flat & 63;
        float4 w = *(const float4*)&Wo[flat];
        *(uint32_t*)&Ks[o * 72 + c]     = packbf(w.x, w.y);
        *(uint32_t*)&Ks[o * 72 + c + 2] = packbf(w.z, w.w);
    }
    __syncthreads();

    // D2 = O * Wo^T : m32 n64 k64
    float pacc[2][8][4];
#pragma unroll
    for (int mb = 0; mb < 2; mb++)
#pragma unroll
        for (int i = 0; i < 8; i++)
#pragma unroll
            for (int k = 0; k < 4; k++) pacc[mb][i][k] = 0.f;

#pragma unroll
    for (int ks4 = 0; ks4 < 4; ks4++) {
        uint32_t A0[4], A1[4];
        LDSM4(A0, aQ0 + ks4 * 32);
        LDSM4(A1, aQ1 + ks4 * 32);
#pragma unroll
        for (int nf2 = 0; nf2 < 4; nf2++) {
            uint32_t Bv[4];
            LDSM4(Bv, sK + ((nf2 * 16 + brow) * 72 + bcol + ks4 * 16) * 2);
            MMA_BF16(pacc[0][nf2 * 2],     A0[0], A0[1], A0[2], A0[3], Bv[0], Bv[1]);
            MMA_BF16(pacc[1][nf2 * 2],     A1[0], A1[1], A1[2], A1[3], Bv[0], Bv[1]);
            MMA_BF16(pacc[0][nf2 * 2 + 1], A0[0], A0[1], A0[2], A0[3], Bv[2], Bv[3]);
            MMA_BF16(pacc[1][nf2 * 2 + 1], A1[0], A1[1], A1[2], A1[3], Bv[2], Bv[3]);
        }
    }

    // stage transposed into Ps region as fp32 [o][t] stride 132
    float* Pf = (float*)(smb + APS_O);
#pragma unroll
    for (int mb = 0; mb < 2; mb++) {
        int t0 = rb + mb * 16 + g, t1 = t0 + 8;
#pragma unroll
        for (int nf = 0; nf < 8; nf++) {
            int o = nf * 8 + 2 * c4;
            Pf[o * 132 + t0]       = pacc[mb][nf][0];
            Pf[(o + 1) * 132 + t0] = pacc[mb][nf][1];
            Pf[o * 132 + t1]       = pacc[mb][nf][2];
            Pf[(o + 1) * 132 + t1] = pacc[mb][nf][3];
        }
    }
    __syncthreads();

    // out[o][t] = proj + x, coalesced float4
    const float* xb = x + (size_t)n * C * T + j * TILE;
    float* ob = out + (size_t)n * C * T + j * TILE;
#pragma unroll
    for (int it = 0; it < 16; it++) {
        int flat = it * 512 + tid * 4;
        int o = flat >> 7, t = flat & 127;
        float4 v  = *(const float4*)&Pf[o * 132 + t];
        float4 xr = *(const float4*)&xb[o * T + t];
        float4 r  = make_float4(v.x + xr.x, v.y + xr.y, v.z + xr.z, v.w + xr.w);
        *(float4*)&ob[o * T + t] = r;
    }
}

// ---------------------------------------------------------------------------
extern "C" void kernel_launch(void* const* d_in, const int* in_sizes, int n_in,
                              void* d_out, int out_size)
{
    const float* x     = (const float*)d_in[0];
    const float* Wq    = (const float*)d_in[1];
    const float* Wk    = (const float*)d_in[2];
    const float* Wv    = (const float*)d_in[3];
    const float* Wo    = (const float*)d_in[4];
    const float* scale = (const float*)d_in[5];
    float* out = (float*)d_out;

    const int smem1 = QKV_SMEM_BF * 2;     // 63488 B
    const int smem2 = ATTN_SMEM_BF * 2;    // 89088 B
    cudaFuncSetAttribute(qkv_kernel,  cudaFuncAttributeMaxDynamicSharedMemorySize, smem1);
    cudaFuncSetAttribute(attn_kernel, cudaFuncAttributeMaxDynamicSharedMemorySize, smem2);

    dim3 grid(8, 128);
    qkv_kernel<<<grid, 256, smem1>>>(x, Wq, Wk, Wv, scale);
    attn_kernel<<<grid, 128, smem2>>>(x, Wo, out);
}

// round 9
// speedup vs baseline: 8.3323x; 1.1054x over previous
#include <cuda_runtime.h>
#include <cuda_bf16.h>
#include <cstdint>

#define NB 128
#define C 64
#define T 1024
#define TILE 128
#define NTILE 8

// bf16 scratch: Q,K t-major [n][t][c] (Q has scale*log2e folded), V [n][c][t].
__device__ __nv_bfloat16 g_Qb[NB * T * C];
__device__ __nv_bfloat16 g_Kb[NB * T * C];
__device__ __nv_bfloat16 g_Vb[NB * C * T];

__device__ __forceinline__ float ex2a(float x) {
    float y;
    asm("ex2.approx.ftz.f32 %0, %1;" : "=f"(y) : "f"(x));
    return y;
}
__device__ __forceinline__ uint32_t packbf(float lo, float hi) {
    __nv_bfloat162 v = __floats2bfloat162_rn(lo, hi);
    return *(uint32_t*)&v;
}
__device__ __forceinline__ uint32_t ldu32(const __nv_bfloat16* p) {
    return *(const uint32_t*)p;
}
__device__ __forceinline__ uint32_t smaddr(const void* p) {
    uint32_t a;
    asm("{ .reg .u64 t; cvta.to.shared.u64 t, %1; cvt.u32.u64 %0, t; }" : "=r"(a) : "l"(p));
    return a;
}

#define MMA_BF16(d, a0, a1, a2, a3, b0, b1)                                   \
    asm volatile(                                                             \
        "mma.sync.aligned.m16n8k16.row.col.f32.bf16.bf16.f32 "                \
        "{%0,%1,%2,%3}, {%4,%5,%6,%7}, {%8,%9}, {%0,%1,%2,%3};"               \
        : "+f"(d[0]), "+f"(d[1]), "+f"(d[2]), "+f"(d[3])                      \
        : "r"(a0), "r"(a1), "r"(a2), "r"(a3), "r"(b0), "r"(b1))

#define LDSM4(R, a)                                                           \
    asm volatile("ldmatrix.sync.aligned.m8n8.x4.shared.b16 {%0,%1,%2,%3}, [%4];" \
        : "=r"((R)[0]), "=r"((R)[1]), "=r"((R)[2]), "=r"((R)[3]) : "r"(a))

// ---------------------------------------------------------------------------
// Kernel 1: QKV projection via bf16 mma.sync (unchanged). 256 thr.
// ---------------------------------------------------------------------------
#define XT_O  0
#define WS_O  9216
#define VST_O (9216 + 13824)
#define QKV_SMEM_BF (VST_O + 8704)     // 31744 bf16 = 63488 B

extern "C" __global__ void __launch_bounds__(256)
qkv_kernel(const float* __restrict__ x,
           const float* __restrict__ Wq,
           const float* __restrict__ Wk,
           const float* __restrict__ Wv,
           const float* __restrict__ scale_p)
{
    extern __shared__ __nv_bfloat16 smb[];
    __nv_bfloat16* xT  = smb + XT_O;
    __nv_bfloat16* Ws  = smb + WS_O;
    __nv_bfloat16* Vst = smb + VST_O;

    const int j = blockIdx.x, n = blockIdx.y;
    const int tid = threadIdx.x;
    const int warp = tid >> 5, lane = tid & 31;
    const int g = lane >> 2, c4 = lane & 3;
    const int rb = warp * 16;
    const float qs = scale_p[0] * 1.44269504088896f;

    const float* xb = x + (size_t)n * C * T + j * TILE;
    for (int idx = tid; idx < 8192; idx += 256) {
        int c = idx >> 7, t = idx & 127;
        xT[t * 72 + c] = __float2bfloat16(xb[c * T + t]);
    }
    for (int idx = tid; idx < 4096; idx += 256) {
        int o = idx >> 6, c = idx & 63;
        Ws[o * 72 + c]            = __float2bfloat16(Wq[idx]);
        Ws[4608 + o * 72 + c]     = __float2bfloat16(Wk[idx]);
        Ws[2 * 4608 + o * 72 + c] = __float2bfloat16(Wv[idx]);
    }
    __syncthreads();

    for (int m = 0; m < 3; m++) {
        float acc[8][4];
#pragma unroll
        for (int i = 0; i < 8; i++)
#pragma unroll
            for (int k = 0; k < 4; k++) acc[i][k] = 0.f;

        const __nv_bfloat16* Wm = Ws + m * 4608;
#pragma unroll
        for (int ks = 0; ks < 4; ks++) {
            int co = ks * 16 + 2 * c4;
            uint32_t a0 = ldu32(&xT[(rb + g) * 72 + co]);
            uint32_t a1 = ldu32(&xT[(rb + g + 8) * 72 + co]);
            uint32_t a2 = ldu32(&xT[(rb + g) * 72 + co + 8]);
            uint32_t a3 = ldu32(&xT[(rb + g + 8) * 72 + co + 8]);
#pragma unroll
            for (int nf = 0; nf < 8; nf++) {
                uint32_t b0 = ldu32(&Wm[(nf * 8 + g) * 72 + co]);
                uint32_t b1 = ldu32(&Wm[(nf * 8 + g) * 72 + co + 8]);
                MMA_BF16(acc[nf], a0, a1, a2, a3, b0, b1);
            }
        }

        if (m == 0) {
#pragma unroll
            for (int i = 0; i < 8; i++)
#pragma unroll
                for (int k = 0; k < 4; k++) acc[i][k] *= qs;
        }

        if (m < 2) {
            __nv_bfloat16* dst = (m == 0 ? g_Qb : g_Kb) + ((size_t)n * T + j * TILE) * C;
            int r0 = rb + g, r1 = rb + g + 8;
#pragma unroll
            for (int nf = 0; nf < 8; nf++) {
                int o = nf * 8 + 2 * c4;
                *(uint32_t*)&dst[r0 * 64 + o] = packbf(acc[nf][0], acc[nf][1]);
                *(uint32_t*)&dst[r1 * 64 + o] = packbf(acc[nf][2], acc[nf][3]);
            }
        } else {
            int r0 = rb + g, r1 = rb + g + 8;
#pragma unroll
            for (int nf = 0; nf < 8; nf++) {
                int o = nf * 8 + 2 * c4;
                Vst[o * 136 + r0]       = __float2bfloat16(acc[nf][0]);
                Vst[(o + 1) * 136 + r0] = __float2bfloat16(acc[nf][1]);
                Vst[o * 136 + r1]       = __float2bfloat16(acc[nf][2]);
                Vst[(o + 1) * 136 + r1] = __float2bfloat16(acc[nf][3]);
            }
        }
    }
    __syncthreads();

    __nv_bfloat16* vdst = g_Vb + (size_t)n * C * T + j * TILE;
#pragma unroll
    for (int it = 0; it < 4; it++) {
        int flat = it * 2048 + tid * 8;
        int r = flat >> 7, t = flat & 127;
        float4 v = *(const float4*)&Vst[r * 136 + t];
        *(float4*)&vdst[r * T + t] = v;
    }
}

// ---------------------------------------------------------------------------
// Kernel 2: attention. 128 threads (4 warps x m32). P stays in registers:
// S accumulator fragment == PV A-operand fragment (FA2 trick). 3 CTAs/SM.
// smem: Qs[128][72] Ks[128][72] Vs[64][136] bf16 = 54272 B.
// Epilogue fp32 staging Pf[64][132] (33792 B) overlays Ks+Vs (offset 18432,
// ends 52224 <= 54272) -- Qs stays live as the D2 A operand.
// ---------------------------------------------------------------------------
#define AQS_O 0
#define AKS_O 9216
#define AVS_O 18432
#define ATTN_SMEM_BF (AVS_O + 8704)    // 27136 bf16 = 54272 B

extern "C" __global__ void __launch_bounds__(128, 3)
attn_kernel(const float* __restrict__ x,
            const float* __restrict__ Wo,
            float* __restrict__ out)
{
    extern __shared__ __nv_bfloat16 smb[];
    __nv_bfloat16* Qs = smb + AQS_O;
    __nv_bfloat16* Ks = smb + AKS_O;
    __nv_bfloat16* Vs = smb + AVS_O;

    const int j = blockIdx.x, n = blockIdx.y;
    const int tid = threadIdx.x;
    const int warp = tid >> 5, lane = tid & 31;
    const int g = lane >> 2, c4 = lane & 3;
    const int rb = warp * 32;

    // ldmatrix lane roles
    const int arow = ((lane >> 3) & 1) * 8 + (lane & 7);  // A: row offset
    const int acol = (lane >> 4) * 8;                     // A: col offset
    const int brow = (lane >> 4) * 8 + (lane & 7);        // B: row offset
    const int bcol = ((lane >> 3) & 1) * 8;               // B: col offset

    const uint32_t sQ = smaddr(Qs);
    const uint32_t sK = smaddr(Ks);
    const uint32_t sV = smaddr(Vs);

    // load Q tile [128][64] bf16 -> stride 72
    const __nv_bfloat16* qsrc = g_Qb + ((size_t)n * T + j * TILE) * C;
#pragma unroll
    for (int it = 0; it < 8; it++) {
        int flat = it * 1024 + tid * 8;
        int r = flat >> 6, c = flat & 63;
        float4 v = *(const float4*)&qsrc[flat];
        *(float4*)&Qs[r * 72 + c] = v;
    }

    const __nv_bfloat16* kbase = g_Kb + (size_t)n * T * C;
    const __nv_bfloat16* vbase = g_Vb + (size_t)n * C * T;

    float lsum[2][2] = {{0.f, 0.f}, {0.f, 0.f}};
    float oacc[2][8][4];
#pragma unroll
    for (int mb = 0; mb < 2; mb++)
#pragma unroll
        for (int i = 0; i < 8; i++)
#pragma unroll
            for (int k = 0; k < 4; k++) oacc[mb][i][k] = 0.f;

    const uint32_t aQ0 = sQ + ((rb + arow) * 72 + acol) * 2;
    const uint32_t aQ1 = aQ0 + 16 * 72 * 2;

    for (int st = 0; st < NTILE; st++) {
        __syncthreads();   // prev PV done; safe to overwrite Ks/Vs
        const __nv_bfloat16* ks = kbase + (size_t)st * TILE * C;
#pragma unroll
        for (int it = 0; it < 8; it++) {
            int flat = it * 1024 + tid * 8;
            int r = flat >> 6, c = flat & 63;
            float4 v = *(const float4*)&ks[flat];
            *(float4*)&Ks[r * 72 + c] = v;
        }
        const __nv_bfloat16* vs = vbase + st * TILE;
#pragma unroll
        for (int it = 0; it < 8; it++) {
            int flat = it * 1024 + tid * 8;
            int r = flat >> 7, t = flat & 127;
            float4 v = *(const float4*)&vs[r * T + t];
            *(float4*)&Vs[r * 136 + t] = v;
        }
        __syncthreads();

        // per 64-col half: S = QK^T -> exp2 -> pack to A-fragments -> PV
#pragma unroll
        for (int hn = 0; hn < 2; hn++) {
            float sacc[2][8][4];
#pragma unroll
            for (int mb = 0; mb < 2; mb++)
#pragma unroll
                for (int i = 0; i < 8; i++)
#pragma unroll
                    for (int k = 0; k < 4; k++) sacc[mb][i][k] = 0.f;

#pragma unroll
            for (int ks4 = 0; ks4 < 4; ks4++) {
                uint32_t A0[4], A1[4];
                LDSM4(A0, aQ0 + ks4 * 32);
                LDSM4(A1, aQ1 + ks4 * 32);
#pragma unroll
                for (int nf2 = 0; nf2 < 4; nf2++) {
                    uint32_t Bv[4];
                    LDSM4(Bv, sK + ((hn * 64 + nf2 * 16 + brow) * 72 +
                                    bcol + ks4 * 16) * 2);
                    MMA_BF16(sacc[0][nf2 * 2],     A0[0], A0[1], A0[2], A0[3], Bv[0], Bv[1]);
                    MMA_BF16(sacc[1][nf2 * 2],     A1[0], A1[1], A1[2], A1[3], Bv[0], Bv[1]);
                    MMA_BF16(sacc[0][nf2 * 2 + 1], A0[0], A0[1], A0[2], A0[3], Bv[2], Bv[3]);
                    MMA_BF16(sacc[1][nf2 * 2 + 1], A1[0], A1[1], A1[2], A1[3], Bv[2], Bv[3]);
                }
            }

            // exp2 + row-sum + pack: S acc fragment -> PV A fragment (registers)
            uint32_t pfrag[2][4][4];   // [mb][k16 chunk j][a0..a3]
#pragma unroll
            for (int mb = 0; mb < 2; mb++) {
#pragma unroll
                for (int jj = 0; jj < 4; jj++) {
                    float e00 = ex2a(sacc[mb][2 * jj][0]);
                    float e01 = ex2a(sacc[mb][2 * jj][1]);
                    float e02 = ex2a(sacc[mb][2 * jj][2]);
                    float e03 = ex2a(sacc[mb][2 * jj][3]);
                    float e10 = ex2a(sacc[mb][2 * jj + 1][0]);
                    float e11 = ex2a(sacc[mb][2 * jj + 1][1]);
                    float e12 = ex2a(sacc[mb][2 * jj + 1][2]);
                    float e13 = ex2a(sacc[mb][2 * jj + 1][3]);
                    lsum[mb][0] += (e00 + e01) + (e10 + e11);
                    lsum[mb][1] += (e02 + e03) + (e12 + e13);
                    pfrag[mb][jj][0] = packbf(e00, e01);
                    pfrag[mb][jj][1] = packbf(e02, e03);
                    pfrag[mb][jj][2] = packbf(e10, e11);
                    pfrag[mb][jj][3] = packbf(e12, e13);
                }
            }

            // O += P V^T for this half's k-range (k = hn*64 .. +63)
#pragma unroll
            for (int jj = 0; jj < 4; jj++) {
#pragma unroll
                for (int nf2 = 0; nf2 < 4; nf2++) {
                    uint32_t Bv[4];
                    LDSM4(Bv, sV + ((nf2 * 16 + brow) * 136 +
                                    bcol + (hn * 4 + jj) * 16) * 2);
                    MMA_BF16(oacc[0][nf2 * 2],     pfrag[0][jj][0], pfrag[0][jj][1],
                             pfrag[0][jj][2], pfrag[0][jj][3], Bv[0], Bv[1]);
                    MMA_BF16(oacc[1][nf2 * 2],     pfrag[1][jj][0], pfrag[1][jj][1],
                             pfrag[1][jj][2], pfrag[1][jj][3], Bv[0], Bv[1]);
                    MMA_BF16(oacc[0][nf2 * 2 + 1], pfrag[0][jj][0], pfrag[0][jj][1],
                             pfrag[0][jj][2], pfrag[0][jj][3], Bv[2], Bv[3]);
                    MMA_BF16(oacc[1][nf2 * 2 + 1], pfrag[1][jj][0], pfrag[1][jj][1],
                             pfrag[1][jj][2], pfrag[1][jj][3], Bv[2], Bv[3]);
                }
            }
        }
    }

    // row sums -> normalize
#pragma unroll
    for (int mb = 0; mb < 2; mb++)
#pragma unroll
        for (int h = 0; h < 2; h++) {
            lsum[mb][h] += __shfl_xor_sync(0xffffffffu, lsum[mb][h], 1);
            lsum[mb][h] += __shfl_xor_sync(0xffffffffu, lsum[mb][h], 2);
        }
    float inv00 = 1.0f / lsum[0][0], inv01 = 1.0f / lsum[0][1];
    float inv10 = 1.0f / lsum[1][0], inv11 = 1.0f / lsum[1][1];

    // O (bf16, normalized) -> Qs (own rows) as [tq][c] stride 72
#pragma unroll
    for (int mb = 0; mb < 2; mb++) {
        int r0 = rb + mb * 16 + g, r1 = r0 + 8;
        float i0 = mb ? inv10 : inv00, i1 = mb ? inv11 : inv01;
#pragma unroll
        for (int nf = 0; nf < 8; nf++) {
            int o = nf * 8 + 2 * c4;
            *(uint32_t*)&Qs[r0 * 72 + o] = packbf(oacc[mb][nf][0] * i0, oacc[mb][nf][1] * i0);
            *(uint32_t*)&Qs[r1 * 72 + o] = packbf(oacc[mb][nf][2] * i1, oacc[mb][nf][3] * i1);
        }
    }
    __syncthreads();   // all warps past last Ks/Vs reads

    // Wo -> Ks as [o][c] bf16 stride 72
#pragma unroll
    for (int it = 0; it < 8; it++) {
        int flat = it * 512 + tid * 4;
        int o = flat >> 6, c = flat & 63;
        float4 w = *(const float4*)&Wo[flat];
        *(uint32_t*)&Ks[o * 72 + c]     = packbf(w.x, w.y);
        *(uint32_t*)&Ks[o * 72 + c + 2] = packbf(w.z, w.w);
    }
    __syncthreads();

    // D2 = O * Wo^T : m32 n64 k64
    const uint32_t aO0 = sQ + ((rb + arow) * 72 + acol) * 2;
    const uint32_t aO1 = aO0 + 16 * 72 * 2;
    float pacc[2][8][4];
#pragma unroll
    for (int mb = 0; mb < 2; mb++)
#pragma unroll
        for (int i = 0; i < 8; i++)
#pragma unroll
            for (int k = 0; k < 4; k++) pacc[mb][i][k] = 0.f;

#pragma unroll
    for (int ks4 = 0; ks4 < 4; ks4++) {
        uint32_t A0[4], A1[4];
        LDSM4(A0, aO0 + ks4 * 32);
        LDSM4(A1, aO1 + ks4 * 32);
#pragma unroll
        for (int nf2 = 0; nf2 < 4; nf2++) {
            uint32_t Bv[4];
            LDSM4(Bv, sK + ((nf2 * 16 + brow) * 72 + bcol + ks4 * 16) * 2);
            MMA_BF16(pacc[0][nf2 * 2],     A0[0], A0[1], A0[2], A0[3], Bv[0], Bv[1]);
            MMA_BF16(pacc[1][nf2 * 2],     A1[0], A1[1], A1[2], A1[3], Bv[0], Bv[1]);
            MMA_BF16(pacc[0][nf2 * 2 + 1], A0[0], A0[1], A0[2], A0[3], Bv[2], Bv[3]);
            MMA_BF16(pacc[1][nf2 * 2 + 1], A1[0], A1[1], A1[2], A1[3], Bv[2], Bv[3]);
        }
    }
    __syncthreads();   // all warps done reading Ks (Wo) before Pf overwrites it

    // stage transposed as fp32 [o][t] stride 132 at the Ks offset:
    // bytes 18432..52224 of 54272-B smem (Qs untouched).
    float* Pf = (float*)(smb + AKS_O);
#pragma unroll
    for (int mb = 0; mb < 2; mb++) {
        int t0 = rb + mb * 16 + g, t1 = t0 + 8;
#pragma unroll
        for (int nf = 0; nf < 8; nf++) {
            int o = nf * 8 + 2 * c4;
            Pf[o * 132 + t0]       = pacc[mb][nf][0];
            Pf[(o + 1) * 132 + t0] = pacc[mb][nf][1];
            Pf[o * 132 + t1]       = pacc[mb][nf][2];
            Pf[(o + 1) * 132 + t1] = pacc[mb][nf][3];
        }
    }
    __syncthreads();

    // out[o][t] = proj + x, coalesced float4
    const float* xb = x + (size_t)n * C * T + j * TILE;
    float* ob = out + (size_t)n * C * T + j * TILE;
#pragma unroll
    for (int it = 0; it < 16; it++) {
        int flat = it * 512 + tid * 4;
        int o = flat >> 7, t = flat & 127;
        float4 v  = *(const float4*)&Pf[o * 132 + t];
        float4 xr = *(const float4*)&xb[o * T + t];
        float4 r  = make_float4(v.x + xr.x, v.y + xr.y, v.z + xr.z, v.w + xr.w);
        *(float4*)&ob[o * T + t] = r;
    }
}

// ---------------------------------------------------------------------------
extern "C" void kernel_launch(void* const* d_in, const int* in_sizes, int n_in,
                              void* d_out, int out_size)
{
    const float* x     = (const float*)d_in[0];
    const float* Wq    = (const float*)d_in[1];
    const float* Wk    = (const float*)d_in[2];
    const float* Wv    = (const float*)d_in[3];
    const float* Wo    = (const float*)d_in[4];
    const float* scale = (const float*)d_in[5];
    float* out = (float*)d_out;

    const int smem1 = QKV_SMEM_BF * 2;     // 63488 B
    const int smem2 = ATTN_SMEM_BF * 2;    // 54272 B
    cudaFuncSetAttribute(qkv_kernel,  cudaFuncAttributeMaxDynamicSharedMemorySize, smem1);
    cudaFuncSetAttribute(attn_kernel, cudaFuncAttributeMaxDynamicSharedMemorySize, smem2);

    dim3 grid(8, 128);
    qkv_kernel<<<grid, 256, smem1>>>(x, Wq, Wk, Wv, scale);
    attn_kernel<<<grid, 128, smem2>>>(x, Wo, out);
}

// round 10
// speedup vs baseline: 8.4568x; 1.0149x over previous
#include <cuda_runtime.h>
#include <cuda_bf16.h>
#include <cstdint>

#define NB 128
#define C 64
#define T 1024
#define TILE 128
#define NTILE 8

// bf16 scratch, ALL t-major [n][t][c]; Q has scale*log2e folded in.
__device__ __nv_bfloat16 g_Qb[NB * T * C];
__device__ __nv_bfloat16 g_Kb[NB * T * C];
__device__ __nv_bfloat16 g_Vb[NB * T * C];

__device__ __forceinline__ float ex2a(float x) {
    float y;
    asm("ex2.approx.ftz.f32 %0, %1;" : "=f"(y) : "f"(x));
    return y;
}
__device__ __forceinline__ uint32_t packbf(float lo, float hi) {
    __nv_bfloat162 v = __floats2bfloat162_rn(lo, hi);
    return *(uint32_t*)&v;
}
__device__ __forceinline__ uint32_t smaddr(const void* p) {
    uint32_t a;
    asm("{ .reg .u64 t; cvta.to.shared.u64 t, %1; cvt.u32.u64 %0, t; }" : "=r"(a) : "l"(p));
    return a;
}

#define MMA_BF16(d, a0, a1, a2, a3, b0, b1)                                   \
    asm volatile(                                                             \
        "mma.sync.aligned.m16n8k16.row.col.f32.bf16.bf16.f32 "                \
        "{%0,%1,%2,%3}, {%4,%5,%6,%7}, {%8,%9}, {%0,%1,%2,%3};"               \
        : "+f"(d[0]), "+f"(d[1]), "+f"(d[2]), "+f"(d[3])                      \
        : "r"(a0), "r"(a1), "r"(a2), "r"(a3), "r"(b0), "r"(b1))

#define LDSM4(R, a)                                                           \
    asm volatile("ldmatrix.sync.aligned.m8n8.x4.shared.b16 {%0,%1,%2,%3}, [%4];" \
        : "=r"((R)[0]), "=r"((R)[1]), "=r"((R)[2]), "=r"((R)[3]) : "r"(a))

#define LDSM4T(R, a)                                                          \
    asm volatile("ldmatrix.sync.aligned.m8n8.x4.trans.shared.b16 {%0,%1,%2,%3}, [%4];" \
        : "=r"((R)[0]), "=r"((R)[1]), "=r"((R)[2]), "=r"((R)[3]) : "r"(a))

// ---------------------------------------------------------------------------
// Kernel 1: QKV projection. 128 threads (4 warps x m32), ldmatrix fragments.
// smem: xT [128][72] + Ws 3x[64][72] = 46080 B. 4 CTAs/SM.
// Outputs Q,K,V all t-major [t][c].
// ---------------------------------------------------------------------------
#define XT_O  0
#define WS_O  9216
#define QKV_SMEM_BF (WS_O + 13824)     // 23040 bf16 = 46080 B

extern "C" __global__ void __launch_bounds__(128, 4)
qkv_kernel(const float* __restrict__ x,
           const float* __restrict__ Wq,
           const float* __restrict__ Wk,
           const float* __restrict__ Wv,
           const float* __restrict__ scale_p)
{
    extern __shared__ __nv_bfloat16 smb[];
    __nv_bfloat16* xT = smb + XT_O;
    __nv_bfloat16* Ws = smb + WS_O;

    const int j = blockIdx.x, n = blockIdx.y;
    const int tid = threadIdx.x;
    const int warp = tid >> 5, lane = tid & 31;
    const int g = lane >> 2, c4 = lane & 3;
    const int rb = warp * 32;
    const float qs = scale_p[0] * 1.44269504088896f;

    // ldmatrix lane roles
    const int arow = ((lane >> 3) & 1) * 8 + (lane & 7);
    const int acol = (lane >> 4) * 8;
    const int brow = (lane >> 4) * 8 + (lane & 7);
    const int bcol = ((lane >> 3) & 1) * 8;

    // x [c][t] fp32 -> xT [t][c] bf16 (float4 global reads)
    const float* xb = x + (size_t)n * C * T + j * TILE;
    for (int idx = tid; idx < 2048; idx += 128) {
        int c = idx >> 5, t4 = (idx & 31) * 4;
        float4 v = *(const float4*)&xb[c * T + t4];
        xT[(t4 + 0) * 72 + c] = __float2bfloat16(v.x);
        xT[(t4 + 1) * 72 + c] = __float2bfloat16(v.y);
        xT[(t4 + 2) * 72 + c] = __float2bfloat16(v.z);
        xT[(t4 + 3) * 72 + c] = __float2bfloat16(v.w);
    }
    // weights [o][c] fp32 -> bf16, stride 72 (float4 reads, paired stores)
    for (int idx = tid; idx < 1024; idx += 128) {
        int o = idx >> 4, cc = (idx & 15) * 4;
        float4 wq = *(const float4*)&Wq[o * 64 + cc];
        float4 wk = *(const float4*)&Wk[o * 64 + cc];
        float4 wv = *(const float4*)&Wv[o * 64 + cc];
        *(uint32_t*)&Ws[o * 72 + cc]            = packbf(wq.x, wq.y);
        *(uint32_t*)&Ws[o * 72 + cc + 2]        = packbf(wq.z, wq.w);
        *(uint32_t*)&Ws[4608 + o * 72 + cc]     = packbf(wk.x, wk.y);
        *(uint32_t*)&Ws[4608 + o * 72 + cc + 2] = packbf(wk.z, wk.w);
        *(uint32_t*)&Ws[9216 + o * 72 + cc]     = packbf(wv.x, wv.y);
        *(uint32_t*)&Ws[9216 + o * 72 + cc + 2] = packbf(wv.z, wv.w);
    }
    __syncthreads();

    const uint32_t sX = smaddr(xT);
    const uint32_t sW = smaddr(Ws);
    const uint32_t aX0 = sX + ((rb + arow) * 72 + acol) * 2;
    const uint32_t aX1 = aX0 + 16 * 72 * 2;

    for (int m = 0; m < 3; m++) {
        float acc[2][8][4];
#pragma unroll
        for (int mb = 0; mb < 2; mb++)
#pragma unroll
            for (int i = 0; i < 8; i++)
#pragma unroll
                for (int k = 0; k < 4; k++) acc[mb][i][k] = 0.f;

        const uint32_t wbase = sW + m * 4608 * 2;
#pragma unroll
        for (int ks4 = 0; ks4 < 4; ks4++) {
            uint32_t A0[4], A1[4];
            LDSM4(A0, aX0 + ks4 * 32);
            LDSM4(A1, aX1 + ks4 * 32);
#pragma unroll
            for (int nf2 = 0; nf2 < 4; nf2++) {
                uint32_t Bv[4];
                LDSM4(Bv, wbase + ((nf2 * 16 + brow) * 72 + bcol + ks4 * 16) * 2);
                MMA_BF16(acc[0][nf2 * 2],     A0[0], A0[1], A0[2], A0[3], Bv[0], Bv[1]);
                MMA_BF16(acc[1][nf2 * 2],     A1[0], A1[1], A1[2], A1[3], Bv[0], Bv[1]);
                MMA_BF16(acc[0][nf2 * 2 + 1], A0[0], A0[1], A0[2], A0[3], Bv[2], Bv[3]);
                MMA_BF16(acc[1][nf2 * 2 + 1], A1[0], A1[1], A1[2], A1[3], Bv[2], Bv[3]);
            }
        }

        if (m == 0) {
#pragma unroll
            for (int mb = 0; mb < 2; mb++)
#pragma unroll
                for (int i = 0; i < 8; i++)
#pragma unroll
                    for (int k = 0; k < 4; k++) acc[mb][i][k] *= qs;
        }

        __nv_bfloat16* dst = (m == 0 ? g_Qb : (m == 1 ? g_Kb : g_Vb))
                             + ((size_t)n * T + j * TILE) * C;
#pragma unroll
        for (int mb = 0; mb < 2; mb++) {
            int r0 = rb + mb * 16 + g, r1 = r0 + 8;
#pragma unroll
            for (int nf = 0; nf < 8; nf++) {
                int o = nf * 8 + 2 * c4;
                *(uint32_t*)&dst[r0 * 64 + o] = packbf(acc[mb][nf][0], acc[mb][nf][1]);
                *(uint32_t*)&dst[r1 * 64 + o] = packbf(acc[mb][nf][2], acc[mb][nf][3]);
            }
        }
    }
}

// ---------------------------------------------------------------------------
// Kernel 2: attention. 128 threads (4 warps x m32). P in registers (FA2).
// V t-major, PV B-fragments via ldmatrix.trans. 3 CTAs/SM.
// smem: Qs[128][72] Ks[128][72] Vs[128][72] bf16 = 55296 B.
// Epilogue Pf[64][132] fp32 (33792 B) overlays Ks+Vs (18432..52224).
// ---------------------------------------------------------------------------
#define AQS_O 0
#define AKS_O 9216
#define AVS_O 18432
#define ATTN_SMEM_BF (AVS_O + 9216)    // 27648 bf16 = 55296 B

extern "C" __global__ void __launch_bounds__(128, 3)
attn_kernel(const float* __restrict__ x,
            const float* __restrict__ Wo,
            float* __restrict__ out)
{
    extern __shared__ __nv_bfloat16 smb[];
    __nv_bfloat16* Qs = smb + AQS_O;
    __nv_bfloat16* Ks = smb + AKS_O;
    __nv_bfloat16* Vs = smb + AVS_O;

    const int j = blockIdx.x, n = blockIdx.y;
    const int tid = threadIdx.x;
    const int warp = tid >> 5, lane = tid & 31;
    const int g = lane >> 2, c4 = lane & 3;
    const int rb = warp * 32;

    // ldmatrix lane roles
    const int arow = ((lane >> 3) & 1) * 8 + (lane & 7);  // A & trans-B rows
    const int acol = (lane >> 4) * 8;                     // A col offset
    const int brow = (lane >> 4) * 8 + (lane & 7);        // B rows (non-trans)
    const int bcol = ((lane >> 3) & 1) * 8;               // B col offset
    const int vcol = (lane >> 4) * 8;                     // trans-B col offset

    const uint32_t sQ = smaddr(Qs);
    const uint32_t sK = smaddr(Ks);
    const uint32_t sV = smaddr(Vs);

    // load Q tile [128][64] bf16 -> stride 72
    const __nv_bfloat16* qsrc = g_Qb + ((size_t)n * T + j * TILE) * C;
#pragma unroll
    for (int it = 0; it < 8; it++) {
        int flat = it * 1024 + tid * 8;
        int r = flat >> 6, c = flat & 63;
        float4 v = *(const float4*)&qsrc[flat];
        *(float4*)&Qs[r * 72 + c] = v;
    }

    const __nv_bfloat16* kbase = g_Kb + (size_t)n * T * C;
    const __nv_bfloat16* vbase = g_Vb + (size_t)n * T * C;

    float lsum[2][2] = {{0.f, 0.f}, {0.f, 0.f}};
    float oacc[2][8][4];
#pragma unroll
    for (int mb = 0; mb < 2; mb++)
#pragma unroll
        for (int i = 0; i < 8; i++)
#pragma unroll
            for (int k = 0; k < 4; k++) oacc[mb][i][k] = 0.f;

    const uint32_t aQ0 = sQ + ((rb + arow) * 72 + acol) * 2;
    const uint32_t aQ1 = aQ0 + 16 * 72 * 2;

    for (int st = 0; st < NTILE; st++) {
        __syncthreads();   // prev PV done; safe to overwrite Ks/Vs
        const __nv_bfloat16* ks = kbase + (size_t)st * TILE * C;
        const __nv_bfloat16* vs = vbase + (size_t)st * TILE * C;
#pragma unroll
        for (int it = 0; it < 8; it++) {
            int flat = it * 1024 + tid * 8;
            int r = flat >> 6, c = flat & 63;
            *(float4*)&Ks[r * 72 + c] = *(const float4*)&ks[flat];
            *(float4*)&Vs[r * 72 + c] = *(const float4*)&vs[flat];
        }
        __syncthreads();

        // per 64-col half: S = QK^T -> exp2 -> pack to A-fragments -> PV
#pragma unroll
        for (int hn = 0; hn < 2; hn++) {
            float sacc[2][8][4];
#pragma unroll
            for (int mb = 0; mb < 2; mb++)
#pragma unroll
                for (int i = 0; i < 8; i++)
#pragma unroll
                    for (int k = 0; k < 4; k++) sacc[mb][i][k] = 0.f;

#pragma unroll
            for (int ks4 = 0; ks4 < 4; ks4++) {
                uint32_t A0[4], A1[4];
                LDSM4(A0, aQ0 + ks4 * 32);
                LDSM4(A1, aQ1 + ks4 * 32);
#pragma unroll
                for (int nf2 = 0; nf2 < 4; nf2++) {
                    uint32_t Bv[4];
                    LDSM4(Bv, sK + ((hn * 64 + nf2 * 16 + brow) * 72 +
                                    bcol + ks4 * 16) * 2);
                    MMA_BF16(sacc[0][nf2 * 2],     A0[0], A0[1], A0[2], A0[3], Bv[0], Bv[1]);
                    MMA_BF16(sacc[1][nf2 * 2],     A1[0], A1[1], A1[2], A1[3], Bv[0], Bv[1]);
                    MMA_BF16(sacc[0][nf2 * 2 + 1], A0[0], A0[1], A0[2], A0[3], Bv[2], Bv[3]);
                    MMA_BF16(sacc[1][nf2 * 2 + 1], A1[0], A1[1], A1[2], A1[3], Bv[2], Bv[3]);
                }
            }

            // exp2 + row-sum + pack: S acc fragment -> PV A fragment
            uint32_t pfrag[2][4][4];
#pragma unroll
            for (int mb = 0; mb < 2; mb++) {
#pragma unroll
                for (int jj = 0; jj < 4; jj++) {
                    float e00 = ex2a(sacc[mb][2 * jj][0]);
                    float e01 = ex2a(sacc[mb][2 * jj][1]);
                    float e02 = ex2a(sacc[mb][2 * jj][2]);
                    float e03 = ex2a(sacc[mb][2 * jj][3]);
                    float e10 = ex2a(sacc[mb][2 * jj + 1][0]);
                    float e11 = ex2a(sacc[mb][2 * jj + 1][1]);
                    float e12 = ex2a(sacc[mb][2 * jj + 1][2]);
                    float e13 = ex2a(sacc[mb][2 * jj + 1][3]);
                    lsum[mb][0] += (e00 + e01) + (e10 + e11);
                    lsum[mb][1] += (e02 + e03) + (e12 + e13);
                    pfrag[mb][jj][0] = packbf(e00, e01);
                    pfrag[mb][jj][1] = packbf(e02, e03);
                    pfrag[mb][jj][2] = packbf(e10, e11);
                    pfrag[mb][jj][3] = packbf(e12, e13);
                }
            }

            // O += P V : V t-major [t][c], B-fragments via trans ldmatrix
#pragma unroll
            for (int jj = 0; jj < 4; jj++) {
                int kk = hn * 4 + jj;
#pragma unroll
                for (int nf2 = 0; nf2 < 4; nf2++) {
                    uint32_t Bv[4];
                    LDSM4T(Bv, sV + ((kk * 16 + arow) * 72 + nf2 * 16 + vcol) * 2);
                    MMA_BF16(oacc[0][nf2 * 2],     pfrag[0][jj][0], pfrag[0][jj][1],
                             pfrag[0][jj][2], pfrag[0][jj][3], Bv[0], Bv[1]);
                    MMA_BF16(oacc[1][nf2 * 2],     pfrag[1][jj][0], pfrag[1][jj][1],
                             pfrag[1][jj][2], pfrag[1][jj][3], Bv[0], Bv[1]);
                    MMA_BF16(oacc[0][nf2 * 2 + 1], pfrag[0][jj][0], pfrag[0][jj][1],
                             pfrag[0][jj][2], pfrag[0][jj][3], Bv[2], Bv[3]);
                    MMA_BF16(oacc[1][nf2 * 2 + 1], pfrag[1][jj][0], pfrag[1][jj][1],
                             pfrag[1][jj][2], pfrag[1][jj][3], Bv[2], Bv[3]);
                }
            }
        }
    }

    // row sums -> normalize
#pragma unroll
    for (int mb = 0; mb < 2; mb++)
#pragma unroll
        for (int h = 0; h < 2; h++) {
            lsum[mb][h] += __shfl_xor_sync(0xffffffffu, lsum[mb][h], 1);
            lsum[mb][h] += __shfl_xor_sync(0xffffffffu, lsum[mb][h], 2);
        }
    float inv00 = 1.0f / lsum[0][0], inv01 = 1.0f / lsum[0][1];
    float inv10 = 1.0f / lsum[1][0], inv11 = 1.0f / lsum[1][1];

    // O (bf16, normalized) -> Qs (own rows) as [tq][c] stride 72
#pragma unroll
    for (int mb = 0; mb < 2; mb++) {
        int r0 = rb + mb * 16 + g, r1 = r0 + 8;
        float i0 = mb ? inv10 : inv00, i1 = mb ? inv11 : inv01;
#pragma unroll
        for (int nf = 0; nf < 8; nf++) {
            int o = nf * 8 + 2 * c4;
            *(uint32_t*)&Qs[r0 * 72 + o] = packbf(oacc[mb][nf][0] * i0, oacc[mb][nf][1] * i0);
            *(uint32_t*)&Qs[r1 * 72 + o] = packbf(oacc[mb][nf][2] * i1, oacc[mb][nf][3] * i1);
        }
    }
    __syncthreads();   // all warps past last Ks/Vs reads

    // Wo -> Ks as [o][c] bf16 stride 72
#pragma unroll
    for (int it = 0; it < 8; it++) {
        int flat = it * 512 + tid * 4;
        int o = flat >> 6, c = flat & 63;
        float4 w = *(const float4*)&Wo[flat];
        *(uint32_t*)&Ks[o * 72 + c]     = packbf(w.x, w.y);
        *(uint32_t*)&Ks[o * 72 + c + 2] = packbf(w.z, w.w);
    }
    __syncthreads();

    // D2 = O * Wo^T : m32 n64 k64
    const uint32_t aO0 = sQ + ((rb + arow) * 72 + acol) * 2;
    const uint32_t aO1 = aO0 + 16 * 72 * 2;
    float pacc[2][8][4];
#pragma unroll
    for (int mb = 0; mb < 2; mb++)
#pragma unroll
        for (int i = 0; i < 8; i++)
#pragma unroll
            for (int k = 0; k < 4; k++) pacc[mb][i][k] = 0.f;

#pragma unroll
    for (int ks4 = 0; ks4 < 4; ks4++) {
        uint32_t A0[4], A1[4];
        LDSM4(A0, aO0 + ks4 * 32);
        LDSM4(A1, aO1 + ks4 * 32);
#pragma unroll
        for (int nf2 = 0; nf2 < 4; nf2++) {
            uint32_t Bv[4];
            LDSM4(Bv, sK + ((nf2 * 16 + brow) * 72 + bcol + ks4 * 16) * 2);
            MMA_BF16(pacc[0][nf2 * 2],     A0[0], A0[1], A0[2], A0[3], Bv[0], Bv[1]);
            MMA_BF16(pacc[1][nf2 * 2],     A1[0], A1[1], A1[2], A1[3], Bv[0], Bv[1]);
            MMA_BF16(pacc[0][nf2 * 2 + 1], A0[0], A0[1], A0[2], A0[3], Bv[2], Bv[3]);
            MMA_BF16(pacc[1][nf2 * 2 + 1], A1[0], A1[1], A1[2], A1[3], Bv[2], Bv[3]);
        }
    }
    __syncthreads();   // all warps done reading Ks (Wo) before Pf overwrites

    // stage transposed as fp32 [o][t] stride 132 at the Ks offset:
    // bytes 18432..52224 of 55296-B smem (Qs untouched).
    float* Pf = (float*)(smb + AKS_O);
#pragma unroll
    for (int mb = 0; mb < 2; mb++) {
        int t0 = rb + mb * 16 + g, t1 = t0 + 8;
#pragma unroll
        for (int nf = 0; nf < 8; nf++) {
            int o = nf * 8 + 2 * c4;
            Pf[o * 132 + t0]       = pacc[mb][nf][0];
            Pf[(o + 1) * 132 + t0] = pacc[mb][nf][1];
            Pf[o * 132 + t1]       = pacc[mb][nf][2];
            Pf[(o + 1) * 132 + t1] = pacc[mb][nf][3];
        }
    }
    __syncthreads();

    // out[o][t] = proj + x, coalesced float4
    const float* xb = x + (size_t)n * C * T + j * TILE;
    float* ob = out + (size_t)n * C * T + j * TILE;
#pragma unroll
    for (int it = 0; it < 16; it++) {
        int flat = it * 512 + tid * 4;
        int o = flat >> 7, t = flat & 127;
        float4 v  = *(const float4*)&Pf[o * 132 + t];
        float4 xr = *(const float4*)&xb[o * T + t];
        float4 r  = make_float4(v.x + xr.x, v.y + xr.y, v.z + xr.z, v.w + xr.w);
        *(float4*)&ob[o * T + t] = r;
    }
}

// ---------------------------------------------------------------------------
extern "C" void kernel_launch(void* const* d_in, const int* in_sizes, int n_in,
                              void* d_out, int out_size)
{
    const float* x     = (const float*)d_in[0];
    const float* Wq    = (const float*)d_in[1];
    const float* Wk    = (const float*)d_in[2];
    const float* Wv    = (const float*)d_in[3];
    const float* Wo    = (const float*)d_in[4];
    const float* scale = (const float*)d_in[5];
    float* out = (float*)d_out;

    const int smem1 = QKV_SMEM_BF * 2;     // 46080 B
    const int smem2 = ATTN_SMEM_BF * 2;    // 55296 B
    cudaFuncSetAttribute(qkv_kernel,  cudaFuncAttributeMaxDynamicSharedMemorySize, smem1);
    cudaFuncSetAttribute(attn_kernel, cudaFuncAttributeMaxDynamicSharedMemorySize, smem2);

    dim3 grid(8, 128);
    qkv_kernel<<<grid, 128, smem1>>>(x, Wq, Wk, Wv, scale);
    attn_kernel<<<grid, 128, smem2>>>(x, Wo, out);
}

// round 12
// speedup vs baseline: 9.3320x; 1.1035x over previous
#include <cuda_runtime.h>
#include <cuda_bf16.h>
#include <cstdint>

#define NB 128
#define C 64
#define T 1024
#define TILE 128
#define NTILE 8

// bf16 scratch, ALL t-major [n][t][c]; Q has scale*log2e folded in.
__device__ __nv_bfloat16 g_Qb[NB * T * C];
__device__ __nv_bfloat16 g_Kb[NB * T * C];
__device__ __nv_bfloat16 g_Vb[NB * T * C];

__device__ __forceinline__ float ex2a(float x) {
    float y;
    asm("ex2.approx.ftz.f32 %0, %1;" : "=f"(y) : "f"(x));
    return y;
}
__device__ __forceinline__ uint32_t packbf(float lo, float hi) {
    __nv_bfloat162 v = __floats2bfloat162_rn(lo, hi);
    return *(uint32_t*)&v;
}
__device__ __forceinline__ uint32_t smaddr(const void* p) {
    uint32_t a;
    asm("{ .reg .u64 t; cvta.to.shared.u64 t, %1; cvt.u32.u64 %0, t; }" : "=r"(a) : "l"(p));
    return a;
}
__device__ __forceinline__ void cpa16(uint32_t dst, const void* src) {
    asm volatile("cp.async.cg.shared.global [%0], [%1], 16;" :: "r"(dst), "l"(src));
}
#define CP_COMMIT() asm volatile("cp.async.commit_group;" ::: "memory")
#define CP_WAIT(n)  asm volatile("cp.async.wait_group %0;" :: "n"(n) : "memory")

#define MMA_BF16(d, a0, a1, a2, a3, b0, b1)                                   \
    asm volatile(                                                             \
        "mma.sync.aligned.m16n8k16.row.col.f32.bf16.bf16.f32 "                \
        "{%0,%1,%2,%3}, {%4,%5,%6,%7}, {%8,%9}, {%0,%1,%2,%3};"               \
        : "+f"(d[0]), "+f"(d[1]), "+f"(d[2]), "+f"(d[3])                      \
        : "r"(a0), "r"(a1), "r"(a2), "r"(a3), "r"(b0), "r"(b1))

#define LDSM4(R, a)                                                           \
    asm volatile("ldmatrix.sync.aligned.m8n8.x4.shared.b16 {%0,%1,%2,%3}, [%4];" \
        : "=r"((R)[0]), "=r"((R)[1]), "=r"((R)[2]), "=r"((R)[3]) : "r"(a))

#define LDSM4T(R, a)                                                          \
    asm volatile("ldmatrix.sync.aligned.m8n8.x4.trans.shared.b16 {%0,%1,%2,%3}, [%4];" \
        : "=r"((R)[0]), "=r"((R)[1]), "=r"((R)[2]), "=r"((R)[3]) : "r"(a))

// ---------------------------------------------------------------------------
// Kernel 1: QKV projection. 128 threads (4 warps x m32). x stored [c][t] in
// smem (no transpose writes); A-fragments via ldmatrix.trans. 4 CTAs/SM.
// smem: xs [64][136] + Ws 3x[64][72] = 45056 B.
// ---------------------------------------------------------------------------
#define XS_O 0
#define WS_O 8704
#define QKV_SMEM_BF (WS_O + 13824)     // 22528 bf16 = 45056 B

extern "C" __global__ void __launch_bounds__(128, 4)
qkv_kernel(const float* __restrict__ x,
           const float* __restrict__ Wq,
           const float* __restrict__ Wk,
           const float* __restrict__ Wv,
           const float* __restrict__ scale_p)
{
    extern __shared__ __nv_bfloat16 smb[];
    __nv_bfloat16* xs = smb + XS_O;
    __nv_bfloat16* Ws = smb + WS_O;

    const int j = blockIdx.x, n = blockIdx.y;
    const int tid = threadIdx.x;
    const int warp = tid >> 5, lane = tid & 31;
    const int g = lane >> 2, c4 = lane & 3;
    const int rb = warp * 32;
    const float qs = scale_p[0] * 1.44269504088896f;

    // B (weights) lane roles (non-trans)
    const int brow = (lane >> 4) * 8 + (lane & 7);
    const int bcol = ((lane >> 3) & 1) * 8;
    // A-via-trans lane roles (memory is [k][m]): tiles a0..a3 =
    // (m0-7,k0-7),(m8-15,k0-7),(m0-7,k8-15),(m8-15,k8-15)
    const int tkrow = ((lane >> 4) & 1) * 8 + (lane & 7);
    const int tmcol = ((lane >> 3) & 1) * 8;

    // x [c][t] fp32 -> xs [c][t] bf16, coalesced packed stores (no conflicts)
    const float* xb = x + (size_t)n * C * T + j * TILE;
    for (int idx = tid; idx < 2048; idx += 128) {
        int c = idx >> 5, t4 = (idx & 31) * 4;
        float4 v = *(const float4*)&xb[c * T + t4];
        *(uint32_t*)&xs[c * 136 + t4]     = packbf(v.x, v.y);
        *(uint32_t*)&xs[c * 136 + t4 + 2] = packbf(v.z, v.w);
    }
    // weights [o][c] fp32 -> bf16, stride 72
    for (int idx = tid; idx < 1024; idx += 128) {
        int o = idx >> 4, cc = (idx & 15) * 4;
        float4 wq = *(const float4*)&Wq[o * 64 + cc];
        float4 wk = *(const float4*)&Wk[o * 64 + cc];
        float4 wv = *(const float4*)&Wv[o * 64 + cc];
        *(uint32_t*)&Ws[o * 72 + cc]            = packbf(wq.x, wq.y);
        *(uint32_t*)&Ws[o * 72 + cc + 2]        = packbf(wq.z, wq.w);
        *(uint32_t*)&Ws[4608 + o * 72 + cc]     = packbf(wk.x, wk.y);
        *(uint32_t*)&Ws[4608 + o * 72 + cc + 2] = packbf(wk.z, wk.w);
        *(uint32_t*)&Ws[9216 + o * 72 + cc]     = packbf(wv.x, wv.y);
        *(uint32_t*)&Ws[9216 + o * 72 + cc + 2] = packbf(wv.z, wv.w);
    }
    __syncthreads();

    const uint32_t sX = smaddr(xs);
    const uint32_t sW = smaddr(Ws);
    // A-trans base: rows = k (stride 136), cols = m (= t within tile)
    const uint32_t aX0 = sX + (tkrow * 136 + rb + tmcol) * 2;
    const uint32_t aX1 = aX0 + 16 * 2;          // mb=1 -> +16 cols

    for (int m = 0; m < 3; m++) {
        float acc[2][8][4];
#pragma unroll
        for (int mb = 0; mb < 2; mb++)
#pragma unroll
            for (int i = 0; i < 8; i++)
#pragma unroll
                for (int k = 0; k < 4; k++) acc[mb][i][k] = 0.f;

        const uint32_t wbase = sW + m * 4608 * 2;
#pragma unroll
        for (int ks4 = 0; ks4 < 4; ks4++) {
            uint32_t A0[4], A1[4];
            LDSM4T(A0, aX0 + ks4 * (16 * 136 * 2));
            LDSM4T(A1, aX1 + ks4 * (16 * 136 * 2));
#pragma unroll
            for (int nf2 = 0; nf2 < 4; nf2++) {
                uint32_t Bv[4];
                LDSM4(Bv, wbase + ((nf2 * 16 + brow) * 72 + bcol + ks4 * 16) * 2);
                MMA_BF16(acc[0][nf2 * 2],     A0[0], A0[1], A0[2], A0[3], Bv[0], Bv[1]);
                MMA_BF16(acc[1][nf2 * 2],     A1[0], A1[1], A1[2], A1[3], Bv[0], Bv[1]);
                MMA_BF16(acc[0][nf2 * 2 + 1], A0[0], A0[1], A0[2], A0[3], Bv[2], Bv[3]);
                MMA_BF16(acc[1][nf2 * 2 + 1], A1[0], A1[1], A1[2], A1[3], Bv[2], Bv[3]);
            }
        }

        if (m == 0) {
#pragma unroll
            for (int mb = 0; mb < 2; mb++)
#pragma unroll
                for (int i = 0; i < 8; i++)
#pragma unroll
                    for (int k = 0; k < 4; k++) acc[mb][i][k] *= qs;
        }

        __nv_bfloat16* dst = (m == 0 ? g_Qb : (m == 1 ? g_Kb : g_Vb))
                             + ((size_t)n * T + j * TILE) * C;
#pragma unroll
        for (int mb = 0; mb < 2; mb++) {
            int r0 = rb + mb * 16 + g, r1 = r0 + 8;
#pragma unroll
            for (int nf = 0; nf < 8; nf++) {
                int o = nf * 8 + 2 * c4;
                *(uint32_t*)&dst[r0 * 64 + o] = packbf(acc[mb][nf][0], acc[mb][nf][1]);
                *(uint32_t*)&dst[r1 * 64 + o] = packbf(acc[mb][nf][2], acc[mb][nf][3]);
            }
        }
    }
}

// ---------------------------------------------------------------------------
// Kernel 2: attention. 128 threads (4 warps x m32). P in registers (FA2),
// Q fragments hoisted to registers, K/V double-buffered via cp.async.
// smem: Qs[128][72] + 2 stages x (K[128][72] + V[128][72]) = 92160 B. 2 CTAs/SM.
// ---------------------------------------------------------------------------
#define AQS_O 0
#define AB_O  9216                      // bf16 offset of stage buffers
#define STAGE_B 36864                   // bytes per stage (K+V)
#define ATTN_SMEM_BF (AB_O + 2 * 18432) // 46080 bf16 = 92160 B

__device__ __forceinline__ void stage_load(uint32_t dstbase,
                                           const __nv_bfloat16* ks,
                                           const __nv_bfloat16* vs, int tid) {
#pragma unroll
    for (int it = 0; it < 8; it++) {
        int flat = it * 128 + tid;
        int r = flat >> 3, cg = flat & 7;
        uint32_t off = (uint32_t)(r * 72 + cg * 8) * 2;
        cpa16(dstbase + off,         ks + r * 64 + cg * 8);
        cpa16(dstbase + 18432 + off, vs + r * 64 + cg * 8);
    }
}

extern "C" __global__ void __launch_bounds__(128, 2)
attn_kernel(const float* __restrict__ x,
            const float* __restrict__ Wo,
            float* __restrict__ out)
{
    extern __shared__ __nv_bfloat16 smb[];
    __nv_bfloat16* Qs = smb + AQS_O;

    const int j = blockIdx.x, n = blockIdx.y;
    const int tid = threadIdx.x;
    const int warp = tid >> 5, lane = tid & 31;
    const int g = lane >> 2, c4 = lane & 3;
    const int rb = warp * 32;

    // ldmatrix lane roles
    const int arow = ((lane >> 3) & 1) * 8 + (lane & 7);  // A rows / trans-B rows
    const int acol = (lane >> 4) * 8;                     // A col offset
    const int brow = (lane >> 4) * 8 + (lane & 7);        // B rows (non-trans)
    const int bcol = ((lane >> 3) & 1) * 8;               // B col offset
    const int vcol = (lane >> 4) * 8;                     // trans-B col offset

    const uint32_t sQ = smaddr(Qs);
    const uint32_t sB = smaddr(smb + AB_O);

    const __nv_bfloat16* kbase = g_Kb + (size_t)n * T * C;
    const __nv_bfloat16* vbase = g_Vb + (size_t)n * T * C;

    // load Q tile [128][64] bf16 -> stride 72
    const __nv_bfloat16* qsrc = g_Qb + ((size_t)n * T + j * TILE) * C;
#pragma unroll
    for (int it = 0; it < 8; it++) {
        int flat = it * 1024 + tid * 8;
        int r = flat >> 6, c = flat & 63;
        float4 v = *(const float4*)&qsrc[flat];
        *(float4*)&Qs[r * 72 + c] = v;
    }
    // prefetch stage 0
    stage_load(sB, kbase, vbase, tid);
    CP_COMMIT();
    __syncthreads();

    // hoist Q fragments (Qs never re-read in mainloop)
    uint32_t QF[4][2][4];
    {
        const uint32_t aQ0 = sQ + ((rb + arow) * 72 + acol) * 2;
        const uint32_t aQ1 = aQ0 + 16 * 72 * 2;
#pragma unroll
        for (int ks4 = 0; ks4 < 4; ks4++) {
            LDSM4(QF[ks4][0], aQ0 + ks4 * 32);
            LDSM4(QF[ks4][1], aQ1 + ks4 * 32);
        }
    }

    float lsum[2][2] = {{0.f, 0.f}, {0.f, 0.f}};
    float oacc[2][8][4];
#pragma unroll
    for (int mb = 0; mb < 2; mb++)
#pragma unroll
        for (int i = 0; i < 8; i++)
#pragma unroll
            for (int k = 0; k < 4; k++) oacc[mb][i][k] = 0.f;

    for (int st = 0; st < NTILE; st++) {
        if (st > 0) __syncthreads();   // all warps done computing st-1
        if (st < 7) {
            stage_load(sB + ((st + 1) & 1) * STAGE_B,
                       kbase + (size_t)(st + 1) * TILE * C,
                       vbase + (size_t)(st + 1) * TILE * C, tid);
            CP_COMMIT();
            CP_WAIT(1);                // stage st complete (only st+1 pending)
        } else {
            CP_WAIT(0);
        }
        __syncthreads();               // stage st visible to all warps

        const uint32_t sK = sB + (st & 1) * STAGE_B;
        const uint32_t sV = sK + 18432;

        // per 64-col half: S = QK^T -> exp2 -> pack to A-fragments -> PV
#pragma unroll
        for (int hn = 0; hn < 2; hn++) {
            float sacc[2][8][4];
#pragma unroll
            for (int mb = 0; mb < 2; mb++)
#pragma unroll
                for (int i = 0; i < 8; i++)
#pragma unroll
                    for (int k = 0; k < 4; k++) sacc[mb][i][k] = 0.f;

#pragma unroll
            for (int ks4 = 0; ks4 < 4; ks4++) {
#pragma unroll
                for (int nf2 = 0; nf2 < 4; nf2++) {
                    uint32_t Bv[4];
                    LDSM4(Bv, sK + ((hn * 64 + nf2 * 16 + brow) * 72 +
                                    bcol + ks4 * 16) * 2);
                    MMA_BF16(sacc[0][nf2 * 2],     QF[ks4][0][0], QF[ks4][0][1],
                             QF[ks4][0][2], QF[ks4][0][3], Bv[0], Bv[1]);
                    MMA_BF16(sacc[1][nf2 * 2],     QF[ks4][1][0], QF[ks4][1][1],
                             QF[ks4][1][2], QF[ks4][1][3], Bv[0], Bv[1]);
                    MMA_BF16(sacc[0][nf2 * 2 + 1], QF[ks4][0][0], QF[ks4][0][1],
                             QF[ks4][0][2], QF[ks4][0][3], Bv[2], Bv[3]);
                    MMA_BF16(sacc[1][nf2 * 2 + 1], QF[ks4][1][0], QF[ks4][1][1],
                             QF[ks4][1][2], QF[ks4][1][3], Bv[2], Bv[3]);
                }
            }

            // exp2 + row-sum + pack: S acc fragment -> PV A fragment
            uint32_t pfrag[2][4][4];
#pragma unroll
            for (int mb = 0; mb < 2; mb++) {
#pragma unroll
                for (int jj = 0; jj < 4; jj++) {
                    float e00 = ex2a(sacc[mb][2 * jj][0]);
                    float e01 = ex2a(sacc[mb][2 * jj][1]);
                    float e02 = ex2a(sacc[mb][2 * jj][2]);
                    float e03 = ex2a(sacc[mb][2 * jj][3]);
                    float e10 = ex2a(sacc[mb][2 * jj + 1][0]);
                    float e11 = ex2a(sacc[mb][2 * jj + 1][1]);
                    float e12 = ex2a(sacc[mb][2 * jj + 1][2]);
                    float e13 = ex2a(sacc[mb][2 * jj + 1][3]);
                    lsum[mb][0] += (e00 + e01) + (e10 + e11);
                    lsum[mb][1] += (e02 + e03) + (e12 + e13);
                    pfrag[mb][jj][0] = packbf(e00, e01);
                    pfrag[mb][jj][1] = packbf(e02, e03);
                    pfrag[mb][jj][2] = packbf(e10, e11);
                    pfrag[mb][jj][3] = packbf(e12, e13);
                }
            }

            // O += P V : V t-major [t][c], B-fragments via trans ldmatrix
#pragma unroll
            for (int jj = 0; jj < 4; jj++) {
                int kk = hn * 4 + jj;
#pragma unroll
                for (int nf2 = 0; nf2 < 4; nf2++) {
                    uint32_t Bv[4];
                    LDSM4T(Bv, sV + ((kk * 16 + arow) * 72 + nf2 * 16 + vcol) * 2);
                    MMA_BF16(oacc[0][nf2 * 2],     pfrag[0][jj][0], pfrag[0][jj][1],
                             pfrag[0][jj][2], pfrag[0][jj][3], Bv[0], Bv[1]);
                    MMA_BF16(oacc[1][nf2 * 2],     pfrag[1][jj][0], pfrag[1][jj][1],
                             pfrag[1][jj][2], pfrag[1][jj][3], Bv[0], Bv[1]);
                    MMA_BF16(oacc[0][nf2 * 2 + 1], pfrag[0][jj][0], pfrag[0][jj][1],
                             pfrag[0][jj][2], pfrag[0][jj][3], Bv[2], Bv[3]);
                    MMA_BF16(oacc[1][nf2 * 2 + 1], pfrag[1][jj][0], pfrag[1][jj][1],
                             pfrag[1][jj][2], pfrag[1][jj][3], Bv[2], Bv[3]);
                }
            }
        }
    }

    // row sums -> normalize
#pragma unroll
    for (int mb = 0; mb < 2; mb++)
#pragma unroll
        for (int h = 0; h < 2; h++) {
            lsum[mb][h] += __shfl_xor_sync(0xffffffffu, lsum[mb][h], 1);
            lsum[mb][h] += __shfl_xor_sync(0xffffffffu, lsum[mb][h], 2);
        }
    float inv00 = 1.0f / lsum[0][0], inv01 = 1.0f / lsum[0][1];
    float inv10 = 1.0f / lsum[1][0], inv11 = 1.0f / lsum[1][1];

    // O (bf16, normalized) -> Qs (own rows, QF already consumed) as [tq][c]
#pragma unroll
    for (int mb = 0; mb < 2; mb++) {
        int r0 = rb + mb * 16 + g, r1 = r0 + 8;
        float i0 = mb ? inv10 : inv00, i1 = mb ? inv11 : inv01;
#pragma unroll
        for (int nf = 0; nf < 8; nf++) {
            int o = nf * 8 + 2 * c4;
            *(uint32_t*)&Qs[r0 * 72 + o] = packbf(oacc[mb][nf][0] * i0, oacc[mb][nf][1] * i0);
            *(uint32_t*)&Qs[r1 * 72 + o] = packbf(oacc[mb][nf][2] * i1, oacc[mb][nf][3] * i1);
        }
    }
    // Wo -> buf0 K region as [o][c] bf16 stride 72 (stage buffers are dead)
    __nv_bfloat16* Wos = smb + AB_O;
#pragma unroll
    for (int it = 0; it < 8; it++) {
        int flat = it * 512 + tid * 4;
        int o = flat >> 6, c = flat & 63;
        float4 w = *(const float4*)&Wo[flat];
        *(uint32_t*)&Wos[o * 72 + c]     = packbf(w.x, w.y);
        *(uint32_t*)&Wos[o * 72 + c + 2] = packbf(w.z, w.w);
    }
    __syncthreads();

    // D2 = O * Wo^T : m32 n64 k64
    const uint32_t sWo = smaddr(Wos);
    const uint32_t aO0 = sQ + ((rb + arow) * 72 + acol) * 2;
    const uint32_t aO1 = aO0 + 16 * 72 * 2;
    float pacc[2][8][4];
#pragma unroll
    for (int mb = 0; mb < 2; mb++)
#pragma unroll
        for (int i = 0; i < 8; i++)
#pragma unroll
            for (int k = 0; k < 4; k++) pacc[mb][i][k] = 0.f;

#pragma unroll
    for (int ks4 = 0; ks4 < 4; ks4++) {
        uint32_t A0[4], A1[4];
        LDSM4(A0, aO0 + ks4 * 32);
        LDSM4(A1, aO1 + ks4 * 32);
#pragma unroll
        for (int nf2 = 0; nf2 < 4; nf2++) {
            uint32_t Bv[4];
            LDSM4(Bv, sWo + ((nf2 * 16 + brow) * 72 + bcol + ks4 * 16) * 2);
            MMA_BF16(pacc[0][nf2 * 2],     A0[0], A0[1], A0[2], A0[3], Bv[0], Bv[1]);
            MMA_BF16(pacc[1][nf2 * 2],     A1[0], A1[1], A1[2], A1[3], Bv[0], Bv[1]);
            MMA_BF16(pacc[0][nf2 * 2 + 1], A0[0], A0[1], A0[2], A0[3], Bv[2], Bv[3]);
            MMA_BF16(pacc[1][nf2 * 2 + 1], A1[0], A1[1], A1[2], A1[3], Bv[2], Bv[3]);
        }
    }

    // stage transposed as fp32 [o][t] stride 132 AFTER the Wo region:
    // bytes 27648..61440 of 92160-B smem (disjoint from Qs and Wo).
    float* Pf = (float*)(smb + AB_O + 4608);
#pragma unroll
    for (int mb = 0; mb < 2; mb++) {
        int t0 = rb + mb * 16 + g, t1 = t0 + 8;
#pragma unroll
        for (int nf = 0; nf < 8; nf++) {
            int o = nf * 8 + 2 * c4;
            Pf[o * 132 + t0]       = pacc[mb][nf][0];
            Pf[(o + 1) * 132 + t0] = pacc[mb][nf][1];
            Pf[o * 132 + t1]       = pacc[mb][nf][2];
            Pf[(o + 1) * 132 + t1] = pacc[mb][nf][3];
        }
    }
    __syncthreads();

    // out[o][t] = proj + x, coalesced float4
    const float* xb = x + (size_t)n * C * T + j * TILE;
    float* ob = out + (size_t)n * C * T + j * TILE;
#pragma unroll
    for (int it = 0; it < 16; it++) {
        int flat = it * 512 + tid * 4;
        int o = flat >> 7, t = flat & 127;
        float4 v  = *(const float4*)&Pf[o * 132 + t];
        float4 xr = *(const float4*)&xb[o * T + t];
        float4 r  = make_float4(v.x + xr.x, v.y + xr.y, v.z + xr.z, v.w + xr.w);
        *(float4*)&ob[o * T + t] = r;
    }
}

// ---------------------------------------------------------------------------
extern "C" void kernel_launch(void* const* d_in, const int* in_sizes, int n_in,
                              void* d_out, int out_size)
{
    const float* x     = (const float*)d_in[0];
    const float* Wq    = (const float*)d_in[1];
    const float* Wk    = (const float*)d_in[2];
    const float* Wv    = (const float*)d_in[3];
    const float* Wo    = (const float*)d_in[4];
    const float* scale = (const float*)d_in[5];
    float* out = (float*)d_out;

    const int smem1 = QKV_SMEM_BF * 2;     // 45056 B
    const int smem2 = ATTN_SMEM_BF * 2;    // 92160 B
    cudaFuncSetAttribute(qkv_kernel,  cudaFuncAttributeMaxDynamicSharedMemorySize, smem1);
    cudaFuncSetAttribute(attn_kernel, cudaFuncAttributeMaxDynamicSharedMemorySize, smem2);

    dim3 grid(8, 128);
    qkv_kernel<<<grid, 128, smem1>>>(x, Wq, Wk, Wv, scale);
    attn_kernel<<<grid, 128, smem2>>>(x, Wo, out);
}

// round 14
// speedup vs baseline: 9.5093x; 1.0190x over previous
#include <cuda_runtime.h>
#include <cuda_bf16.h>
#include <cstdint>

#define NB 128
#define C 64
#define T 1024
#define TILE 128
#define NSUB 16          // 64-row s-subtiles

// bf16 scratch, ALL t-major [n][t][c]; Q has scale*log2e folded in.
__device__ __nv_bfloat16 g_Qb[NB * T * C];
__device__ __nv_bfloat16 g_Kb[NB * T * C];
__device__ __nv_bfloat16 g_Vb[NB * T * C];

__device__ __forceinline__ float ex2a(float x) {
    float y;
    asm("ex2.approx.ftz.f32 %0, %1;" : "=f"(y) : "f"(x));
    return y;
}
__device__ __forceinline__ uint32_t packbf(float lo, float hi) {
    __nv_bfloat162 v = __floats2bfloat162_rn(lo, hi);
    return *(uint32_t*)&v;
}
__device__ __forceinline__ uint32_t smaddr(const void* p) {
    uint32_t a;
    asm("{ .reg .u64 t; cvta.to.shared.u64 t, %1; cvt.u32.u64 %0, t; }" : "=r"(a) : "l"(p));
    return a;
}
__device__ __forceinline__ void cpa16(uint32_t dst, const void* src) {
    asm volatile("cp.async.cg.shared.global [%0], [%1], 16;" :: "r"(dst), "l"(src));
}
#define CP_COMMIT() asm volatile("cp.async.commit_group;" ::: "memory")
#define CP_WAIT(n)  asm volatile("cp.async.wait_group %0;" :: "n"(n) : "memory")

#define MMA_BF16(d, a0, a1, a2, a3, b0, b1)                                   \
    asm volatile(                                                             \
        "mma.sync.aligned.m16n8k16.row.col.f32.bf16.bf16.f32 "                \
        "{%0,%1,%2,%3}, {%4,%5,%6,%7}, {%8,%9}, {%0,%1,%2,%3};"               \
        : "+f"(d[0]), "+f"(d[1]), "+f"(d[2]), "+f"(d[3])                      \
        : "r"(a0), "r"(a1), "r"(a2), "r"(a3), "r"(b0), "r"(b1))

#define LDSM4(R, a)                                                           \
    asm volatile("ldmatrix.sync.aligned.m8n8.x4.shared.b16 {%0,%1,%2,%3}, [%4];" \
        : "=r"((R)[0]), "=r"((R)[1]), "=r"((R)[2]), "=r"((R)[3]) : "r"(a))

#define LDSM4T(R, a)                                                          \
    asm volatile("ldmatrix.sync.aligned.m8n8.x4.trans.shared.b16 {%0,%1,%2,%3}, [%4];" \
        : "=r"((R)[0]), "=r"((R)[1]), "=r"((R)[2]), "=r"((R)[3]) : "r"(a))

// ---------------------------------------------------------------------------
// Kernel 1: QKV projection. 128 threads (4 warps x m32). x stored [c][t],
// A-fragments via ldmatrix.trans; outputs staged in smem for coalesced
// gmem writes. 3 CTAs/SM.
// smem: xs [64][136] + Ws 3x[64][72] + stg [128][72] = 63488 B.
// (stg stride 72 bf16 = 144 B, 16B-aligned for float4 copy-out.)
// ---------------------------------------------------------------------------
#define XS_O  0
#define WS_O  8704
#define STG_O 22528
#define QKV_SMEM_BF (STG_O + 9216)     // 31744 bf16 = 63488 B

extern "C" __global__ void __launch_bounds__(128, 3)
qkv_kernel(const float* __restrict__ x,
           const float* __restrict__ Wq,
           const float* __restrict__ Wk,
           const float* __restrict__ Wv,
           const float* __restrict__ scale_p)
{
    extern __shared__ __nv_bfloat16 smb[];
    __nv_bfloat16* xs  = smb + XS_O;
    __nv_bfloat16* Ws  = smb + WS_O;
    __nv_bfloat16* stg = smb + STG_O;

    const int j = blockIdx.x, n = blockIdx.y;
    const int tid = threadIdx.x;
    const int warp = tid >> 5, lane = tid & 31;
    const int g = lane >> 2, c4 = lane & 3;
    const int rb = warp * 32;
    const float qs = scale_p[0] * 1.44269504088896f;

    // B (weights) lane roles (non-trans)
    const int brow = (lane >> 4) * 8 + (lane & 7);
    const int bcol = ((lane >> 3) & 1) * 8;
    // A-via-trans lane roles (memory is [k][m])
    const int tkrow = ((lane >> 4) & 1) * 8 + (lane & 7);
    const int tmcol = ((lane >> 3) & 1) * 8;

    // x [c][t] fp32 -> xs [c][t] bf16, coalesced packed stores
    const float* xb = x + (size_t)n * C * T + j * TILE;
    for (int idx = tid; idx < 2048; idx += 128) {
        int c = idx >> 5, t4 = (idx & 31) * 4;
        float4 v = *(const float4*)&xb[c * T + t4];
        *(uint32_t*)&xs[c * 136 + t4]     = packbf(v.x, v.y);
        *(uint32_t*)&xs[c * 136 + t4 + 2] = packbf(v.z, v.w);
    }
    // weights [o][c] fp32 -> bf16, stride 72
    for (int idx = tid; idx < 1024; idx += 128) {
        int o = idx >> 4, cc = (idx & 15) * 4;
        float4 wq = *(const float4*)&Wq[o * 64 + cc];
        float4 wk = *(const float4*)&Wk[o * 64 + cc];
        float4 wv = *(const float4*)&Wv[o * 64 + cc];
        *(uint32_t*)&Ws[o * 72 + cc]            = packbf(wq.x, wq.y);
        *(uint32_t*)&Ws[o * 72 + cc + 2]        = packbf(wq.z, wq.w);
        *(uint32_t*)&Ws[4608 + o * 72 + cc]     = packbf(wk.x, wk.y);
        *(uint32_t*)&Ws[4608 + o * 72 + cc + 2] = packbf(wk.z, wk.w);
        *(uint32_t*)&Ws[9216 + o * 72 + cc]     = packbf(wv.x, wv.y);
        *(uint32_t*)&Ws[9216 + o * 72 + cc + 2] = packbf(wv.z, wv.w);
    }
    __syncthreads();

    const uint32_t sX = smaddr(xs);
    const uint32_t sW = smaddr(Ws);
    const uint32_t aX0 = sX + (tkrow * 136 + rb + tmcol) * 2;
    const uint32_t aX1 = aX0 + 16 * 2;

    for (int m = 0; m < 3; m++) {
        float acc[2][8][4];
#pragma unroll
        for (int mb = 0; mb < 2; mb++)
#pragma unroll
            for (int i = 0; i < 8; i++)
#pragma unroll
                for (int k = 0; k < 4; k++) acc[mb][i][k] = 0.f;

        const uint32_t wbase = sW + m * 4608 * 2;
#pragma unroll
        for (int ks4 = 0; ks4 < 4; ks4++) {
            uint32_t A0[4], A1[4];
            LDSM4T(A0, aX0 + ks4 * (16 * 136 * 2));
            LDSM4T(A1, aX1 + ks4 * (16 * 136 * 2));
#pragma unroll
            for (int nf2 = 0; nf2 < 4; nf2++) {
                uint32_t Bv[4];
                LDSM4(Bv, wbase + ((nf2 * 16 + brow) * 72 + bcol + ks4 * 16) * 2);
                MMA_BF16(acc[0][nf2 * 2],     A0[0], A0[1], A0[2], A0[3], Bv[0], Bv[1]);
                MMA_BF16(acc[1][nf2 * 2],     A1[0], A1[1], A1[2], A1[3], Bv[0], Bv[1]);
                MMA_BF16(acc[0][nf2 * 2 + 1], A0[0], A0[1], A0[2], A0[3], Bv[2], Bv[3]);
                MMA_BF16(acc[1][nf2 * 2 + 1], A1[0], A1[1], A1[2], A1[3], Bv[2], Bv[3]);
            }
        }

        if (m == 0) {
#pragma unroll
            for (int mb = 0; mb < 2; mb++)
#pragma unroll
                for (int i = 0; i < 8; i++)
#pragma unroll
                    for (int k = 0; k < 4; k++) acc[mb][i][k] *= qs;
        }

        if (m > 0) __syncthreads();   // previous copy out of stg finished
        // fragment stores -> stg [128][72]
#pragma unroll
        for (int mb = 0; mb < 2; mb++) {
            int r0 = rb + mb * 16 + g, r1 = r0 + 8;
#pragma unroll
            for (int nf = 0; nf < 8; nf++) {
                int o = nf * 8 + 2 * c4;
                *(uint32_t*)&stg[r0 * 72 + o] = packbf(acc[mb][nf][0], acc[mb][nf][1]);
                *(uint32_t*)&stg[r1 * 72 + o] = packbf(acc[mb][nf][2], acc[mb][nf][3]);
            }
        }
        __syncthreads();
        // coalesced copy stg -> gmem [t][c]
        __nv_bfloat16* dst = (m == 0 ? g_Qb : (m == 1 ? g_Kb : g_Vb))
                             + ((size_t)n * T + j * TILE) * C;
#pragma unroll
        for (int it = 0; it < 8; it++) {
            int flat = it * 1024 + tid * 8;
            int r = flat >> 6, c = flat & 63;
            *(float4*)&dst[r * 64 + c] = *(const float4*)&stg[r * 72 + c];
        }
    }
}

// ---------------------------------------------------------------------------
// Kernel 2: attention. 128 threads (4 warps x m32). P in registers (FA2),
// 64-row s-subtiles, K/V double-buffered via cp.async. 3 CTAs/SM.
// smem: Qs[128][72] + 2 stages x (K[64][72] + V[64][72]) = 55296 B.
// ---------------------------------------------------------------------------
#define AQS_O 0
#define AB_O  9216                      // bf16 offset of stage buffers
#define STAGE_B 18432                   // bytes per stage (K64 + V64)
#define ATTN_SMEM_BF (AB_O + 2 * 9216)  // 27648 bf16 = 55296 B

__device__ __forceinline__ void stage_load(uint32_t dstbase,
                                           const __nv_bfloat16* ks,
                                           const __nv_bfloat16* vs, int tid) {
#pragma unroll
    for (int it = 0; it < 4; it++) {
        int flat = it * 128 + tid;
        int r = flat >> 3, cg = flat & 7;
        uint32_t off = (uint32_t)(r * 72 + cg * 8) * 2;
        cpa16(dstbase + off,        ks + r * 64 + cg * 8);
        cpa16(dstbase + 9216 + off, vs + r * 64 + cg * 8);
    }
}

extern "C" __global__ void __launch_bounds__(128, 3)
attn_kernel(const float* __restrict__ x,
            const float* __restrict__ Wo,
            float* __restrict__ out)
{
    extern __shared__ __nv_bfloat16 smb[];
    __nv_bfloat16* Qs = smb + AQS_O;

    const int j = blockIdx.x, n = blockIdx.y;
    const int tid = threadIdx.x;
    const int warp = tid >> 5, lane = tid & 31;
    const int g = lane >> 2, c4 = lane & 3;
    const int rb = warp * 32;

    // ldmatrix lane roles
    const int arow = ((lane >> 3) & 1) * 8 + (lane & 7);  // A rows / trans-B rows
    const int acol = (lane >> 4) * 8;                     // A col offset
    const int brow = (lane >> 4) * 8 + (lane & 7);        // B rows (non-trans)
    const int bcol = ((lane >> 3) & 1) * 8;               // B col offset
    const int vcol = (lane >> 4) * 8;                     // trans-B col offset

    const uint32_t sQ = smaddr(Qs);
    const uint32_t sB = smaddr(smb + AB_O);

    const __nv_bfloat16* kbase = g_Kb + (size_t)n * T * C;
    const __nv_bfloat16* vbase = g_Vb + (size_t)n * T * C;

    // load Q tile [128][64] bf16 -> stride 72
    const __nv_bfloat16* qsrc = g_Qb + ((size_t)n * T + j * TILE) * C;
#pragma unroll
    for (int it = 0; it < 8; it++) {
        int flat = it * 1024 + tid * 8;
        int r = flat >> 6, c = flat & 63;
        float4 v = *(const float4*)&qsrc[flat];
        *(float4*)&Qs[r * 72 + c] = v;
    }
    // prefetch stage 0
    stage_load(sB, kbase, vbase, tid);
    CP_COMMIT();

    float lsum[2][2] = {{0.f, 0.f}, {0.f, 0.f}};
    float oacc[2][8][4];
#pragma unroll
    for (int mb = 0; mb < 2; mb++)
#pragma unroll
        for (int i = 0; i < 8; i++)
#pragma unroll
            for (int k = 0; k < 4; k++) oacc[mb][i][k] = 0.f;

    const uint32_t aQ0 = sQ + ((rb + arow) * 72 + acol) * 2;
    const uint32_t aQ1 = aQ0 + 16 * 72 * 2;

    for (int ss = 0; ss < NSUB; ss++) {
        if (ss > 0) __syncthreads();   // all warps done computing ss-1
        if (ss < NSUB - 1) {
            stage_load(sB + ((ss + 1) & 1) * STAGE_B,
                       kbase + (size_t)(ss + 1) * 64 * C,
                       vbase + (size_t)(ss + 1) * 64 * C, tid);
            CP_COMMIT();
            CP_WAIT(1);                // stage ss complete
        } else {
            CP_WAIT(0);
        }
        __syncthreads();               // stage ss visible to all warps

        const uint32_t sK = sB + (ss & 1) * STAGE_B;
        const uint32_t sV = sK + 9216;

        // S = Q K^T (m32 x n64 x k64)
        float sacc[2][8][4];
#pragma unroll
        for (int mb = 0; mb < 2; mb++)
#pragma unroll
            for (int i = 0; i < 8; i++)
#pragma unroll
                for (int k = 0; k < 4; k++) sacc[mb][i][k] = 0.f;

#pragma unroll
        for (int ks4 = 0; ks4 < 4; ks4++) {
            uint32_t A0[4], A1[4];
            LDSM4(A0, aQ0 + ks4 * 32);
            LDSM4(A1, aQ1 + ks4 * 32);
#pragma unroll
            for (int nf2 = 0; nf2 < 4; nf2++) {
                uint32_t Bv[4];
                LDSM4(Bv, sK + ((nf2 * 16 + brow) * 72 + bcol + ks4 * 16) * 2);
                MMA_BF16(sacc[0][nf2 * 2],     A0[0], A0[1], A0[2], A0[3], Bv[0], Bv[1]);
                MMA_BF16(sacc[1][nf2 * 2],     A1[0], A1[1], A1[2], A1[3], Bv[0], Bv[1]);
                MMA_BF16(sacc[0][nf2 * 2 + 1], A0[0], A0[1], A0[2], A0[3], Bv[2], Bv[3]);
                MMA_BF16(sacc[1][nf2 * 2 + 1], A1[0], A1[1], A1[2], A1[3], Bv[2], Bv[3]);
            }
        }

        // exp2 + row-sum + pack: S acc fragment -> PV A fragment
        uint32_t pfrag[2][4][4];
#pragma unroll
        for (int mb = 0; mb < 2; mb++) {
#pragma unroll
            for (int jj = 0; jj < 4; jj++) {
                float e00 = ex2a(sacc[mb][2 * jj][0]);
                float e01 = ex2a(sacc[mb][2 * jj][1]);
                float e02 = ex2a(sacc[mb][2 * jj][2]);
                float e03 = ex2a(sacc[mb][2 * jj][3]);
                float e10 = ex2a(sacc[mb][2 * jj + 1][0]);
                float e11 = ex2a(sacc[mb][2 * jj + 1][1]);
                float e12 = ex2a(sacc[mb][2 * jj + 1][2]);
                float e13 = ex2a(sacc[mb][2 * jj + 1][3]);
                lsum[mb][0] += (e00 + e01) + (e10 + e11);
                lsum[mb][1] += (e02 + e03) + (e12 + e13);
                pfrag[mb][jj][0] = packbf(e00, e01);
                pfrag[mb][jj][1] = packbf(e02, e03);
                pfrag[mb][jj][2] = packbf(e10, e11);
                pfrag[mb][jj][3] = packbf(e12, e13);
            }
        }

        // O += P V (m32 x n64 x k64), V t-major via trans ldmatrix
#pragma unroll
        for (int jj = 0; jj < 4; jj++) {
#pragma unroll
            for (int nf2 = 0; nf2 < 4; nf2++) {
                uint32_t Bv[4];
                LDSM4T(Bv, sV + ((jj * 16 + arow) * 72 + nf2 * 16 + vcol) * 2);
                MMA_BF16(oacc[0][nf2 * 2],     pfrag[0][jj][0], pfrag[0][jj][1],
                         pfrag[0][jj][2], pfrag[0][jj][3], Bv[0], Bv[1]);
                MMA_BF16(oacc[1][nf2 * 2],     pfrag[1][jj][0], pfrag[1][jj][1],
                         pfrag[1][jj][2], pfrag[1][jj][3], Bv[0], Bv[1]);
                MMA_BF16(oacc[0][nf2 * 2 + 1], pfrag[0][jj][0], pfrag[0][jj][1],
                         pfrag[0][jj][2], pfrag[0][jj][3], Bv[2], Bv[3]);
                MMA_BF16(oacc[1][nf2 * 2 + 1], pfrag[1][jj][0], pfrag[1][jj][1],
                         pfrag[1][jj][2], pfrag[1][jj][3], Bv[2], Bv[3]);
            }
        }
    }

    // row sums -> normalize
#pragma unroll
    for (int mb = 0; mb < 2; mb++)
#pragma unroll
        for (int h = 0; h < 2; h++) {
            lsum[mb][h] += __shfl_xor_sync(0xffffffffu, lsum[mb][h], 1);
            lsum[mb][h] += __shfl_xor_sync(0xffffffffu, lsum[mb][h], 2);
        }
    float inv00 = 1.0f / lsum[0][0], inv01 = 1.0f / lsum[0][1];
    float inv10 = 1.0f / lsum[1][0], inv11 = 1.0f / lsum[1][1];

    // O (bf16, normalized) -> Qs (own rows) as [tq][c]
#pragma unroll
    for (int mb = 0; mb < 2; mb++) {
        int r0 = rb + mb * 16 + g, r1 = r0 + 8;
        float i0 = mb ? inv10 : inv00, i1 = mb ? inv11 : inv01;
#pragma unroll
        for (int nf = 0; nf < 8; nf++) {
            int o = nf * 8 + 2 * c4;
            *(uint32_t*)&Qs[r0 * 72 + o] = packbf(oacc[mb][nf][0] * i0, oacc[mb][nf][1] * i0);
            *(uint32_t*)&Qs[r1 * 72 + o] = packbf(oacc[mb][nf][2] * i1, oacc[mb][nf][3] * i1);
        }
    }
    // Wo -> stage region (dead) as [o][c] bf16 stride 72
    __nv_bfloat16* Wos = smb + AB_O;
#pragma unroll
    for (int it = 0; it < 8; it++) {
        int flat = it * 512 + tid * 4;
        int o = flat >> 6, c = flat & 63;
        float4 w = *(const float4*)&Wo[flat];
        *(uint32_t*)&Wos[o * 72 + c]     = packbf(w.x, w.y);
        *(uint32_t*)&Wos[o * 72 + c + 2] = packbf(w.z, w.w);
    }
    __syncthreads();

    // D2 = O * Wo^T : m32 n64 k64
    const uint32_t sWo = smaddr(Wos);
    const uint32_t aO0 = sQ + ((rb + arow) * 72 + acol) * 2;
    const uint32_t aO1 = aO0 + 16 * 72 * 2;
    float pacc[2][8][4];
#pragma unroll
    for (int mb = 0; mb < 2; mb++)
#pragma unroll
        for (int i = 0; i < 8; i++)
#pragma unroll
            for (int k = 0; k < 4; k++) pacc[mb][i][k] = 0.f;

#pragma unroll
    for (int ks4 = 0; ks4 < 4; ks4++) {
        uint32_t A0[4], A1[4];
        LDSM4(A0, aO0 + ks4 * 32);
        LDSM4(A1, aO1 + ks4 * 32);
#pragma unroll
        for (int nf2 = 0; nf2 < 4; nf2++) {
            uint32_t Bv[4];
            LDSM4(Bv, sWo + ((nf2 * 16 + brow) * 72 + bcol + ks4 * 16) * 2);
            MMA_BF16(pacc[0][nf2 * 2],     A0[0], A0[1], A0[2], A0[3], Bv[0], Bv[1]);
            MMA_BF16(pacc[1][nf2 * 2],     A1[0], A1[1], A1[2], A1[3], Bv[0], Bv[1]);
            MMA_BF16(pacc[0][nf2 * 2 + 1], A0[0], A0[1], A0[2], A0[3], Bv[2], Bv[3]);
            MMA_BF16(pacc[1][nf2 * 2 + 1], A1[0], A1[1], A1[2], A1[3], Bv[2], Bv[3]);
        }
    }
    __syncthreads();   // all warps done reading Wos before Pf overwrites

    // stage transposed as fp32 [o][t] stride 132 over the stage region:
    // bytes 18432..52224 of 55296-B smem (Qs untouched).
    float* Pf = (float*)(smb + AB_O);
#pragma unroll
    for (int mb = 0; mb < 2; mb++) {
        int t0 = rb + mb * 16 + g, t1 = t0 + 8;
#pragma unroll
        for (int nf = 0; nf < 8; nf++) {
            int o = nf * 8 + 2 * c4;
            Pf[o * 132 + t0]       = pacc[mb][nf][0];
            Pf[(o + 1) * 132 + t0] = pacc[mb][nf][1];
            Pf[o * 132 + t1]       = pacc[mb][nf][2];
            Pf[(o + 1) * 132 + t1] = pacc[mb][nf][3];
        }
    }
    __syncthreads();

    // out[o][t] = proj + x, coalesced float4
    const float* xb = x + (size_t)n * C * T + j * TILE;
    float* ob = out + (size_t)n * C * T + j * TILE;
#pragma unroll
    for (int it = 0; it < 16; it++) {
        int flat = it * 512 + tid * 4;
        int o = flat >> 7, t = flat & 127;
        float4 v  = *(const float4*)&Pf[o * 132 + t];
        float4 xr = *(const float4*)&xb[o * T + t];
        float4 r  = make_float4(v.x + xr.x, v.y + xr.y, v.z + xr.z, v.w + xr.w);
        *(float4*)&ob[o * T + t] = r;
    }
}

// ---------------------------------------------------------------------------
extern "C" void kernel_launch(void* const* d_in, const int* in_sizes, int n_in,
                              void* d_out, int out_size)
{
    const float* x     = (const float*)d_in[0];
    const float* Wq    = (const float*)d_in[1];
    const float* Wk    = (const float*)d_in[2];
    const float* Wv    = (const float*)d_in[3];
    const float* Wo    = (const float*)d_in[4];
    const float* scale = (const float*)d_in[5];
    float* out = (float*)d_out;

    const int smem1 = QKV_SMEM_BF * 2;     // 63488 B
    const int smem2 = ATTN_SMEM_BF * 2;    // 55296 B
    cudaFuncSetAttribute(qkv_kernel,  cudaFuncAttributeMaxDynamicSharedMemorySize, smem1);
    cudaFuncSetAttribute(attn_kernel, cudaFuncAttributeMaxDynamicSharedMemorySize, smem2);

    dim3 grid(8, 128);
    qkv_kernel<<<grid, 128, smem1>>>(x, Wq, Wk, Wv, scale);
    attn_kernel<<<grid, 128, smem2>>>(x, Wo, out);
}